// round 10
// baseline (speedup 1.0000x reference)
#include <cuda_runtime.h>
#include <cuda_fp16.h>
#include <cstdint>

// AttenConv round 9: fp16 HMMA flash kernel, GEMM2 software-pipelined 1 tile back.
// out[u,:] = softmax_i(adj?<U_u,V_i>:0) @ V @ W
// GEMM1: fp16 hi/lo 3-term emulation; GEMM2: single fp16 term (p' <= 1).
// Round 9: per tile issue GEMM1(t) then GEMM2(t-1) back-to-back (64 MMAs,
// no serial interlude), THEN the epilogue chain. Hi V-plane gets 3 buffers
// (GEMM2 reads one tile behind); lo plane keeps 2.

#define U_DIM   8192
#define I_DIM   16384
#define D_DIM   64
#define OUT_DIM 64
#define BM      32          // users per CTA
#define BN      128         // items per tile
#define NT      (I_DIM / BN)
#define VSTR    144         // bytes per 64-half row (72 halves, conflict-free ldsm)
#define ROWB    18432       // 128 rows * 144B = one tile plane

// smem byte offsets
#define SM_U_HI 0           // U hi fp16 [32][72]   4608
#define SM_U_LO 4608        // U lo fp16 [32][72]   4608
#define SM_DEN  9216        // dens[4][32] fp32 512 + ms[4][32] fp32 512
#define SM_VHI  10240       // hi plane x3 bufs     55296
#define SM_VLO  65536       // lo plane x2 bufs     36864
#define SM_NUMA SM_VHI               // end-phase alias: num [4][32][68] fp32 = 34816
#define SM_WA   SM_VLO               // end-phase alias: W fp32 [64][64] = 16384
#define SMEM_TOTAL 102400

__device__ __align__(16) __half g_vhi[I_DIM][72];
__device__ __align__(16) __half g_vlo[I_DIM][72];

__device__ __forceinline__ uint32_t smem_u32(const void* p) {
    uint32_t a;
    asm("{ .reg .u64 t; cvta.to.shared.u64 t, %1; cvt.u32.u64 %0, t; }" : "=r"(a) : "l"(p));
    return a;
}
__device__ __forceinline__ void cp16(uint32_t dst, const void* src) {
    asm volatile("cp.async.cg.shared.global [%0], [%1], 16;" :: "r"(dst), "l"(src));
}
#define CP_COMMIT() asm volatile("cp.async.commit_group;" ::: "memory")
#define CP_WAIT1()  asm volatile("cp.async.wait_group 1;" ::: "memory")

__device__ __forceinline__ void mma16816(float& d0, float& d1, float& d2, float& d3,
                                         uint32_t a0, uint32_t a1, uint32_t a2, uint32_t a3,
                                         uint32_t b0, uint32_t b1) {
    asm volatile("mma.sync.aligned.m16n8k16.row.col.f32.f16.f16.f32 "
                 "{%0,%1,%2,%3},{%4,%5,%6,%7},{%8,%9},{%0,%1,%2,%3};"
                 : "+f"(d0), "+f"(d1), "+f"(d2), "+f"(d3)
                 : "r"(a0), "r"(a1), "r"(a2), "r"(a3), "r"(b0), "r"(b1));
}
__device__ __forceinline__ void ldsm4(uint32_t& r0, uint32_t& r1, uint32_t& r2, uint32_t& r3,
                                      uint32_t addr) {
    asm volatile("ldmatrix.sync.aligned.m8n8.x4.shared.b16 {%0,%1,%2,%3}, [%4];"
                 : "=r"(r0), "=r"(r1), "=r"(r2), "=r"(r3) : "r"(addr));
}
__device__ __forceinline__ void ldsm4t(uint32_t& r0, uint32_t& r1, uint32_t& r2, uint32_t& r3,
                                       uint32_t addr) {
    asm volatile("ldmatrix.sync.aligned.m8n8.x4.trans.shared.b16 {%0,%1,%2,%3}, [%4];"
                 : "=r"(r0), "=r"(r1), "=r"(r2), "=r"(r3) : "r"(addr));
}
__device__ __forceinline__ uint32_t packh2(float x0, float x1) {
    uint32_t r;
    asm("cvt.rn.f16x2.f32 %0, %1, %2;" : "=r"(r) : "f"(x1), "f"(x0));
    return r;
}
__device__ __forceinline__ void split2h(float x0, float x1, uint32_t& h, uint32_t& l) {
    h = packh2(x0, x1);
    __half2 hv = *(__half2*)&h;
    float2 back = __half22float2(hv);
    l = packh2(x0 - back.x, x1 - back.y);
}

// ---- precompute: split item_emb into fp16 hi/lo planes with VSTR padding ----
__global__ void __launch_bounds__(256)
vsplit_kernel(const float* __restrict__ item_emb)
{
    const int gid  = blockIdx.x * 256 + threadIdx.x;
    const int item = gid >> 3;
    const int d0   = (gid & 7) * 8;
    const float4* vp = (const float4*)(item_emb + (long)item * D_DIM + d0);
    const float4 v0 = vp[0], v1 = vp[1];
    uint32_t h0, l0, h1, l1, h2, l2, h3, l3;
    split2h(v0.x, v0.y, h0, l0); split2h(v0.z, v0.w, h1, l1);
    split2h(v1.x, v1.y, h2, l2); split2h(v1.z, v1.w, h3, l3);
    *(uint4*)&g_vhi[item][d0] = make_uint4(h0, h1, h2, h3);
    *(uint4*)&g_vlo[item][d0] = make_uint4(l0, l1, l2, l3);
}

__global__ void __launch_bounds__(256, 2)
atten_hmma_kernel(const float* __restrict__ user_emb,
                  const float* __restrict__ item_emb,
                  const float* __restrict__ Wmat,
                  const int*   __restrict__ adj,
                  float*       __restrict__ out)
{
    extern __shared__ __align__(128) char smc[];
    const uint32_t sb = smem_u32(smc);
    const int tid = threadIdx.x;
    const int w   = tid >> 5;
    const int l   = tid & 31;
    const int m   = w & 1;          // user group: rows 16m..16m+15
    const int q   = w >> 1;         // item quarter: items 32q..32q+31 in tile
    const int u0  = blockIdx.x * BM;

    const char* vhib = (const char*)g_vhi;
    const char* vlob = (const char*)g_vlo;

    // ---- prologue: stage U hi/lo; cp.async V tile 0 ----
    {
        const int row = tid >> 3, d0 = (tid & 7) * 8;
        const float4* up = (const float4*)(user_emb + (long)(u0 + row) * D_DIM + d0);
        const float4 v0 = up[0], v1 = up[1];
        uint32_t h0, l0h, h1, l1h, h2, l2h, h3, l3h;
        split2h(v0.x, v0.y, h0, l0h); split2h(v0.z, v0.w, h1, l1h);
        split2h(v1.x, v1.y, h2, l2h); split2h(v1.z, v1.w, h3, l3h);
        *(uint4*)(smc + SM_U_HI + row * VSTR + d0 * 2) = make_uint4(h0, h1, h2, h3);
        *(uint4*)(smc + SM_U_LO + row * VSTR + d0 * 2) = make_uint4(l0h, l1h, l2h, l3h);
    }
    for (int idx = tid; idx < 1152; idx += 256) {
        cp16(sb + SM_VHI + idx * 16, vhib + idx * 16);
        cp16(sb + SM_VLO + idx * 16, vlob + idx * 16);
    }
    CP_COMMIT();
    __syncthreads();

    // ---- persistent U A-fragments (hi/lo fp16) ----
    uint32_t auh[4][4], aul[4][4];
    {
        const uint32_t abase = (16 * m + (l & 15)) * VSTR + (l >> 4) * 16;
        #pragma unroll
        for (int kk = 0; kk < 4; kk++) {
            ldsm4(auh[kk][0], auh[kk][1], auh[kk][2], auh[kk][3], sb + SM_U_HI + abase + kk * 32);
            ldsm4(aul[kk][0], aul[kk][1], aul[kk][2], aul[kk][3], sb + SM_U_LO + abase + kk * 32);
        }
    }

    // ldmatrix lane bases within a V plane (quarter q)
    const uint32_t g1base = (32 * q + (l & 7) + (l >> 4) * 8) * VSTR + (((l >> 3) & 1) * 8) * 2;
    const uint32_t g2base = (32 * q + (l & 7) + ((l >> 3) & 1) * 8) * VSTR + (l >> 4) * 16;

    float num[8][4] = {};
    float den0 = 0.f, den1 = 0.f;
    float m0 = 0.f, m1 = 0.f;
    uint32_t pA[4], pB[4];          // P'(t-1) fp16x2 fragments, carried across tiles

    const int r0 = 16 * m + (l >> 2), r1 = r0 + 8;
    const int cb = 2 * (l & 3);
    const long adjr0 = (long)(u0 + r0) * I_DIM + 32 * q + cb;
    const long adjr1 = adjr0 + 8L * I_DIM;

    #pragma unroll 1
    for (int t = 0; t < NT; t++) {
        // stage tile t+1: hi -> buf (t+1)%3, lo -> buf (t+1)%2
        if (t + 1 < NT) {
            const long srcoff = (long)(t + 1) * ROWB;
            const uint32_t dh = sb + SM_VHI + ((t + 1) % 3) * ROWB;
            const uint32_t dl = sb + SM_VLO + ((t + 1) & 1) * ROWB;
            for (int idx = tid; idx < 1152; idx += 256) {
                cp16(dh + idx * 16, vhib + srcoff + idx * 16);
                cp16(dl + idx * 16, vlob + srcoff + idx * 16);
            }
        }
        CP_COMMIT();

        // adj for this tile (overlaps the wait)
        int2 a0r[4], a1r[4];
        {
            const int2* p0 = (const int2*)(adj + adjr0 + (long)t * BN);
            const int2* p1 = (const int2*)(adj + adjr1 + (long)t * BN);
            #pragma unroll
            for (int nt = 0; nt < 4; nt++) { a0r[nt] = p0[4 * nt]; a1r[nt] = p1[4 * nt]; }
        }

        CP_WAIT1();
        __syncthreads();                 // buf t ready

        const uint32_t vhi = sb + SM_VHI + (t % 3) * ROWB;
        const uint32_t vlo = sb + SM_VLO + (t & 1) * ROWB;

        // ---- GEMM1(t): S[16 x 32] = U x V^T (3-term fp16 split) ----
        float s[4][4] = {};
        #pragma unroll
        for (int kk = 0; kk < 4; kk++) {
            #pragma unroll
            for (int jn = 0; jn < 2; jn++) {
                const uint32_t off = jn * (16 * VSTR) + kk * 32;
                uint32_t bh0, bh1, bh2, bh3, bl0, bl1, bl2, bl3;
                ldsm4(bh0, bh1, bh2, bh3, vhi + g1base + off);
                ldsm4(bl0, bl1, bl2, bl3, vlo + g1base + off);
                float* s0 = s[2 * jn];
                float* s1 = s[2 * jn + 1];
                mma16816(s0[0], s0[1], s0[2], s0[3], auh[kk][0], auh[kk][1], auh[kk][2], auh[kk][3], bh0, bh1);
                mma16816(s0[0], s0[1], s0[2], s0[3], auh[kk][0], auh[kk][1], auh[kk][2], auh[kk][3], bl0, bl1);
                mma16816(s0[0], s0[1], s0[2], s0[3], aul[kk][0], aul[kk][1], aul[kk][2], aul[kk][3], bh0, bh1);
                mma16816(s1[0], s1[1], s1[2], s1[3], auh[kk][0], auh[kk][1], auh[kk][2], auh[kk][3], bh2, bh3);
                mma16816(s1[0], s1[1], s1[2], s1[3], auh[kk][0], auh[kk][1], auh[kk][2], auh[kk][3], bl2, bl3);
                mma16816(s1[0], s1[1], s1[2], s1[3], aul[kk][0], aul[kk][1], aul[kk][2], aul[kk][3], bh2, bh3);
            }
        }

        // ---- GEMM2(t-1): num += P'(t-1) x V(t-1) (hi plane, buf (t-1)%3) ----
        // Independent of GEMM1(t) accumulators: fills the tensor pipe while s lands.
        if (t > 0) {
            const uint32_t vhp = sb + SM_VHI + ((t - 1) % 3) * ROWB;
            #pragma unroll
            for (int kk = 0; kk < 2; kk++) {
                const uint32_t ah0 = pA[2 * kk], ah1 = pB[2 * kk], ah2 = pA[2 * kk + 1], ah3 = pB[2 * kk + 1];
                #pragma unroll
                for (int jd = 0; jd < 4; jd++) {
                    const uint32_t off = kk * (16 * VSTR) + jd * 32;
                    uint32_t bh0, bh1, bh2, bh3;
                    ldsm4t(bh0, bh1, bh2, bh3, vhp + g2base + off);
                    float* n0 = num[2 * jd];
                    float* n1 = num[2 * jd + 1];
                    mma16816(n0[0], n0[1], n0[2], n0[3], ah0, ah1, ah2, ah3, bh0, bh1);
                    mma16816(n1[0], n1[1], n1[2], n1[3], ah0, ah1, ah2, ah3, bh2, bh3);
                }
            }
        }

        // ---- epilogue(t): mask, running max, branchless rescale, P'(t) ----
        float mt0 = 0.f, mt1 = 0.f;
        #pragma unroll
        for (int nt = 0; nt < 4; nt++) {
            s[nt][0] = (a0r[nt].x > 0) ? s[nt][0] : 0.f;
            s[nt][1] = (a0r[nt].y > 0) ? s[nt][1] : 0.f;
            s[nt][2] = (a1r[nt].x > 0) ? s[nt][2] : 0.f;
            s[nt][3] = (a1r[nt].y > 0) ? s[nt][3] : 0.f;
            mt0 = fmaxf(mt0, fmaxf(s[nt][0], s[nt][1]));
            mt1 = fmaxf(mt1, fmaxf(s[nt][2], s[nt][3]));
        }
        mt0 = fmaxf(mt0, __shfl_xor_sync(0xffffffffu, mt0, 1));
        mt0 = fmaxf(mt0, __shfl_xor_sync(0xffffffffu, mt0, 2));
        mt1 = fmaxf(mt1, __shfl_xor_sync(0xffffffffu, mt1, 1));
        mt1 = fmaxf(mt1, __shfl_xor_sync(0xffffffffu, mt1, 2));

        const float m0n = fmaxf(m0, mt0), m1n = fmaxf(m1, mt1);
        const float sc0 = __expf(m0 - m0n), sc1 = __expf(m1 - m1n);
        den0 *= sc0; den1 *= sc1;
        #pragma unroll
        for (int nd = 0; nd < 8; nd++) {
            num[nd][0] *= sc0; num[nd][1] *= sc0;
            num[nd][2] *= sc1; num[nd][3] *= sc1;
        }
        m0 = m0n; m1 = m1n;

        #pragma unroll
        for (int nt = 0; nt < 4; nt++) {
            float p00 = __expf(s[nt][0] - m0), p01 = __expf(s[nt][1] - m0);
            float p10 = __expf(s[nt][2] - m1), p11 = __expf(s[nt][3] - m1);
            den0 += p00 + p01;
            den1 += p10 + p11;
            pA[nt] = packh2(p00, p01);
            pB[nt] = packh2(p10, p11);
        }
        __syncthreads();                 // all reads of lobuf/hibuf done before next cp
    }

    // ---- drain: GEMM2(NT-1) ----
    {
        const uint32_t vhp = sb + SM_VHI + ((NT - 1) % 3) * ROWB;
        #pragma unroll
        for (int kk = 0; kk < 2; kk++) {
            const uint32_t ah0 = pA[2 * kk], ah1 = pB[2 * kk], ah2 = pA[2 * kk + 1], ah3 = pB[2 * kk + 1];
            #pragma unroll
            for (int jd = 0; jd < 4; jd++) {
                const uint32_t off = kk * (16 * VSTR) + jd * 32;
                uint32_t bh0, bh1, bh2, bh3;
                ldsm4t(bh0, bh1, bh2, bh3, vhp + g2base + off);
                float* n0 = num[2 * jd];
                float* n1 = num[2 * jd + 1];
                mma16816(n0[0], n0[1], n0[2], n0[3], ah0, ah1, ah2, ah3, bh0, bh1);
                mma16816(n1[0], n1[1], n1[2], n1[3], ah0, ah1, ah2, ah3, bh2, bh3);
            }
        }
    }
    __syncthreads();        // all V reads complete before aliasing smem

    // ---- end phase: merge (m, den, num) across item quarters ----
    float* dens = (float*)(smc + SM_DEN);          // [4][32]
    float* ms   = (float*)(smc + SM_DEN + 512);    // [4][32]
    float* numq = (float*)(smc + SM_NUMA);         // [4][32][68] fp32 (aliases V hi)

    if ((l & 3) == 0) { ms[q * 32 + r0] = m0; ms[q * 32 + r1] = m1; }
    __syncthreads();
    const float M0 = fmaxf(fmaxf(ms[r0], ms[32 + r0]), fmaxf(ms[64 + r0], ms[96 + r0]));
    const float M1 = fmaxf(fmaxf(ms[r1], ms[32 + r1]), fmaxf(ms[64 + r1], ms[96 + r1]));
    const float f0 = __expf(m0 - M0), f1 = __expf(m1 - M1);

    #pragma unroll
    for (int nd = 0; nd < 8; nd++) {
        *(float2*)(numq + q * (32 * 68) + r0 * 68 + 8 * nd + cb) =
            make_float2(num[nd][0] * f0, num[nd][1] * f0);
        *(float2*)(numq + q * (32 * 68) + r1 * 68 + 8 * nd + cb) =
            make_float2(num[nd][2] * f1, num[nd][3] * f1);
    }
    den0 += __shfl_xor_sync(0xffffffffu, den0, 1);
    den0 += __shfl_xor_sync(0xffffffffu, den0, 2);
    den1 += __shfl_xor_sync(0xffffffffu, den1, 1);
    den1 += __shfl_xor_sync(0xffffffffu, den1, 2);
    if ((l & 3) == 0) { dens[q * 32 + r0] = den0 * f0; dens[q * 32 + r1] = den1 * f1; }
    __syncthreads();

    // reduce num across q into q=0 slab; stage W into its alias region
    {
        const int row = tid >> 3, c0 = (tid & 7) * 8;
        float acc[8];
        #pragma unroll
        for (int j = 0; j < 8; j++) acc[j] = numq[row * 68 + c0 + j];
        #pragma unroll
        for (int qq = 1; qq < 4; qq++)
            #pragma unroll
            for (int j = 0; j < 8; j++)
                acc[j] += numq[qq * (32 * 68) + row * 68 + c0 + j];
        #pragma unroll
        for (int j = 0; j < 8; j++) numq[row * 68 + c0 + j] = acc[j];

        const float4* wp = (const float4*)Wmat;
        float4* ws = (float4*)(smc + SM_WA);
        #pragma unroll
        for (int j = 0; j < 4; j++) ws[tid + 256 * j] = wp[tid + 256 * j];
    }
    __syncthreads();

    // GEMM3: out = (num/den) @ W
    {
        const int row = tid >> 3, c0 = (tid & 7) * 8;
        const float dinv = 1.0f / (dens[row] + dens[32 + row] + dens[64 + row] + dens[96 + row]);
        const float* ws = (const float*)(smc + SM_WA);
        float acc[8] = {};
        #pragma unroll 8
        for (int k = 0; k < 64; k++) {
            const float a = numq[row * 68 + k];
            const float4 w0 = *(const float4*)(ws + k * 64 + c0);
            const float4 w1 = *(const float4*)(ws + k * 64 + c0 + 4);
            acc[0] = fmaf(a, w0.x, acc[0]); acc[1] = fmaf(a, w0.y, acc[1]);
            acc[2] = fmaf(a, w0.z, acc[2]); acc[3] = fmaf(a, w0.w, acc[3]);
            acc[4] = fmaf(a, w1.x, acc[4]); acc[5] = fmaf(a, w1.y, acc[5]);
            acc[6] = fmaf(a, w1.z, acc[6]); acc[7] = fmaf(a, w1.w, acc[7]);
        }
        float4* op = (float4*)(out + (long)(u0 + row) * OUT_DIM + c0);
        op[0] = make_float4(acc[0] * dinv, acc[1] * dinv, acc[2] * dinv, acc[3] * dinv);
        op[1] = make_float4(acc[4] * dinv, acc[5] * dinv, acc[6] * dinv, acc[7] * dinv);
    }
}

extern "C" void kernel_launch(void* const* d_in, const int* in_sizes, int n_in,
                              void* d_out, int out_size)
{
    const float* user_emb = (const float*)d_in[0];
    const float* item_emb = (const float*)d_in[1];
    const float* Wmat     = (const float*)d_in[2];
    const int*   adj      = (const int*)d_in[3];
    float*       out      = (float*)d_out;

    vsplit_kernel<<<I_DIM * D_DIM / 8 / 256, 256>>>(item_emb);
    cudaFuncSetAttribute(atten_hmma_kernel,
                         cudaFuncAttributeMaxDynamicSharedMemorySize, SMEM_TOTAL);
    atten_hmma_kernel<<<U_DIM / BM, 256, SMEM_TOTAL>>>(user_emb, item_emb, Wmat, adj, out);
}

// round 11
// speedup vs baseline: 1.0483x; 1.0483x over previous
#include <cuda_runtime.h>
#include <cuda_fp16.h>
#include <cstdint>

// AttenConv round 10: fp16 HMMA flash kernel, ITEM-SPLIT x4 for grid balance.
// out[u,:] = softmax_i(adj?<U_u,V_i>:0) @ V @ W
// GEMM1: fp16 hi/lo 3-term emulation; GEMM2: single fp16 term (p' <= 1).
// Round 10: grid 256 -> 1024 (each CTA does 1/4 of the items, 32 tiles);
// per-SM load drops 2.0 -> ~1.75 CTA-units. Partial (num, den, m) written
// to gmem scratch; a small merge kernel combines quarters and applies W.

#define U_DIM   8192
#define I_DIM   16384
#define D_DIM   64
#define OUT_DIM 64
#define BM      32          // users per CTA
#define BN      128         // items per tile
#define NCH     4           // item chunks (CTAs per u-block)
#define NTC     32          // tiles per CTA = (I_DIM/BN)/NCH
#define VSTR    144         // bytes per 64-half row (72 halves, conflict-free ldsm)
#define ROWB    18432       // 128 rows * 144B = one tile plane

// smem byte offsets
#define SM_U_HI 0           // U hi fp16 [32][72]   4608
#define SM_U_LO 4608        // U lo fp16 [32][72]   4608
#define SM_DEN  9216        // dens[4][32] fp32 512 + ms[4][32] fp32 512
#define SM_VHI  10240       // hi plane x3 bufs     55296
#define SM_VLO  65536       // lo plane x2 bufs     36864
#define SM_NUMA SM_VHI               // end-phase alias: num [4][32][68] fp32 = 34816
#define SMEM_TOTAL 102400

__device__ __align__(16) __half g_vhi[I_DIM][72];
__device__ __align__(16) __half g_vlo[I_DIM][72];
__device__ __align__(16) float  g_pnum[1024][BM][D_DIM];   // 8 MB partial numerators
__device__ float g_pden[1024][BM];
__device__ float g_pm[1024][BM];

__device__ __forceinline__ uint32_t smem_u32(const void* p) {
    uint32_t a;
    asm("{ .reg .u64 t; cvta.to.shared.u64 t, %1; cvt.u32.u64 %0, t; }" : "=r"(a) : "l"(p));
    return a;
}
__device__ __forceinline__ void cp16(uint32_t dst, const void* src) {
    asm volatile("cp.async.cg.shared.global [%0], [%1], 16;" :: "r"(dst), "l"(src));
}
#define CP_COMMIT() asm volatile("cp.async.commit_group;" ::: "memory")
#define CP_WAIT1()  asm volatile("cp.async.wait_group 1;" ::: "memory")

__device__ __forceinline__ void mma16816(float& d0, float& d1, float& d2, float& d3,
                                         uint32_t a0, uint32_t a1, uint32_t a2, uint32_t a3,
                                         uint32_t b0, uint32_t b1) {
    asm volatile("mma.sync.aligned.m16n8k16.row.col.f32.f16.f16.f32 "
                 "{%0,%1,%2,%3},{%4,%5,%6,%7},{%8,%9},{%0,%1,%2,%3};"
                 : "+f"(d0), "+f"(d1), "+f"(d2), "+f"(d3)
                 : "r"(a0), "r"(a1), "r"(a2), "r"(a3), "r"(b0), "r"(b1));
}
__device__ __forceinline__ void ldsm4(uint32_t& r0, uint32_t& r1, uint32_t& r2, uint32_t& r3,
                                      uint32_t addr) {
    asm volatile("ldmatrix.sync.aligned.m8n8.x4.shared.b16 {%0,%1,%2,%3}, [%4];"
                 : "=r"(r0), "=r"(r1), "=r"(r2), "=r"(r3) : "r"(addr));
}
__device__ __forceinline__ void ldsm4t(uint32_t& r0, uint32_t& r1, uint32_t& r2, uint32_t& r3,
                                       uint32_t addr) {
    asm volatile("ldmatrix.sync.aligned.m8n8.x4.trans.shared.b16 {%0,%1,%2,%3}, [%4];"
                 : "=r"(r0), "=r"(r1), "=r"(r2), "=r"(r3) : "r"(addr));
}
__device__ __forceinline__ uint32_t packh2(float x0, float x1) {
    uint32_t r;
    asm("cvt.rn.f16x2.f32 %0, %1, %2;" : "=r"(r) : "f"(x1), "f"(x0));
    return r;
}
__device__ __forceinline__ void split2h(float x0, float x1, uint32_t& h, uint32_t& l) {
    h = packh2(x0, x1);
    __half2 hv = *(__half2*)&h;
    float2 back = __half22float2(hv);
    l = packh2(x0 - back.x, x1 - back.y);
}

// ---- precompute: split item_emb into fp16 hi/lo planes with VSTR padding ----
__global__ void __launch_bounds__(256)
vsplit_kernel(const float* __restrict__ item_emb)
{
    const int gid  = blockIdx.x * 256 + threadIdx.x;
    const int item = gid >> 3;
    const int d0   = (gid & 7) * 8;
    const float4* vp = (const float4*)(item_emb + (long)item * D_DIM + d0);
    const float4 v0 = vp[0], v1 = vp[1];
    uint32_t h0, l0, h1, l1, h2, l2, h3, l3;
    split2h(v0.x, v0.y, h0, l0); split2h(v0.z, v0.w, h1, l1);
    split2h(v1.x, v1.y, h2, l2); split2h(v1.z, v1.w, h3, l3);
    *(uint4*)&g_vhi[item][d0] = make_uint4(h0, h1, h2, h3);
    *(uint4*)&g_vlo[item][d0] = make_uint4(l0, l1, l2, l3);
}

__global__ void __launch_bounds__(256, 2)
atten_hmma_kernel(const float* __restrict__ user_emb,
                  const int*   __restrict__ adj)
{
    extern __shared__ __align__(128) char smc[];
    const uint32_t sb = smem_u32(smc);
    const int tid = threadIdx.x;
    const int bid = blockIdx.x;
    const int ub  = bid >> 2;       // u-block
    const int ch  = bid & 3;        // item chunk
    const int w   = tid >> 5;
    const int l   = tid & 31;
    const int m   = w & 1;          // user group: rows 16m..16m+15
    const int q   = w >> 1;         // item quarter within tile
    const int u0  = ub * BM;
    const int tg0 = ch * NTC;       // first global tile index

    const char* vhib = (const char*)g_vhi;
    const char* vlob = (const char*)g_vlo;

    // ---- prologue: stage U hi/lo; cp.async first V tile ----
    {
        const int row = tid >> 3, d0 = (tid & 7) * 8;
        const float4* up = (const float4*)(user_emb + (long)(u0 + row) * D_DIM + d0);
        const float4 v0 = up[0], v1 = up[1];
        uint32_t h0, l0h, h1, l1h, h2, l2h, h3, l3h;
        split2h(v0.x, v0.y, h0, l0h); split2h(v0.z, v0.w, h1, l1h);
        split2h(v1.x, v1.y, h2, l2h); split2h(v1.z, v1.w, h3, l3h);
        *(uint4*)(smc + SM_U_HI + row * VSTR + d0 * 2) = make_uint4(h0, h1, h2, h3);
        *(uint4*)(smc + SM_U_LO + row * VSTR + d0 * 2) = make_uint4(l0h, l1h, l2h, l3h);
    }
    {
        const long srcoff = (long)tg0 * ROWB;
        for (int idx = tid; idx < 1152; idx += 256) {
            cp16(sb + SM_VHI + idx * 16, vhib + srcoff + idx * 16);
            cp16(sb + SM_VLO + idx * 16, vlob + srcoff + idx * 16);
        }
    }
    CP_COMMIT();
    __syncthreads();

    // ---- persistent U A-fragments (hi/lo fp16) ----
    uint32_t auh[4][4], aul[4][4];
    {
        const uint32_t abase = (16 * m + (l & 15)) * VSTR + (l >> 4) * 16;
        #pragma unroll
        for (int kk = 0; kk < 4; kk++) {
            ldsm4(auh[kk][0], auh[kk][1], auh[kk][2], auh[kk][3], sb + SM_U_HI + abase + kk * 32);
            ldsm4(aul[kk][0], aul[kk][1], aul[kk][2], aul[kk][3], sb + SM_U_LO + abase + kk * 32);
        }
    }

    // ldmatrix lane bases within a V plane (quarter q)
    const uint32_t g1base = (32 * q + (l & 7) + (l >> 4) * 8) * VSTR + (((l >> 3) & 1) * 8) * 2;
    const uint32_t g2base = (32 * q + (l & 7) + ((l >> 3) & 1) * 8) * VSTR + (l >> 4) * 16;

    float num[8][4] = {};
    float den0 = 0.f, den1 = 0.f;
    float m0 = 0.f, m1 = 0.f;
    uint32_t pA[4], pB[4];          // P'(t-1) fp16x2 fragments, carried across tiles

    const int r0 = 16 * m + (l >> 2), r1 = r0 + 8;
    const int cb = 2 * (l & 3);
    const long adjr0 = (long)(u0 + r0) * I_DIM + 32 * q + cb + (long)tg0 * BN;
    const long adjr1 = adjr0 + 8L * I_DIM;

    #pragma unroll 1
    for (int t = 0; t < NTC; t++) {
        // stage tile t+1: hi -> buf (t+1)%3, lo -> buf (t+1)%2
        if (t + 1 < NTC) {
            const long srcoff = (long)(tg0 + t + 1) * ROWB;
            const uint32_t dh = sb + SM_VHI + ((t + 1) % 3) * ROWB;
            const uint32_t dl = sb + SM_VLO + ((t + 1) & 1) * ROWB;
            for (int idx = tid; idx < 1152; idx += 256) {
                cp16(dh + idx * 16, vhib + srcoff + idx * 16);
                cp16(dl + idx * 16, vlob + srcoff + idx * 16);
            }
        }
        CP_COMMIT();

        // adj for this tile (overlaps the wait)
        int2 a0r[4], a1r[4];
        {
            const int2* p0 = (const int2*)(adj + adjr0 + (long)t * BN);
            const int2* p1 = (const int2*)(adj + adjr1 + (long)t * BN);
            #pragma unroll
            for (int nt = 0; nt < 4; nt++) { a0r[nt] = p0[4 * nt]; a1r[nt] = p1[4 * nt]; }
        }

        CP_WAIT1();
        __syncthreads();                 // buf t ready

        const uint32_t vhi = sb + SM_VHI + (t % 3) * ROWB;
        const uint32_t vlo = sb + SM_VLO + (t & 1) * ROWB;

        // ---- GEMM1(t): S[16 x 32] = U x V^T (3-term fp16 split) ----
        float s[4][4] = {};
        #pragma unroll
        for (int kk = 0; kk < 4; kk++) {
            #pragma unroll
            for (int jn = 0; jn < 2; jn++) {
                const uint32_t off = jn * (16 * VSTR) + kk * 32;
                uint32_t bh0, bh1, bh2, bh3, bl0, bl1, bl2, bl3;
                ldsm4(bh0, bh1, bh2, bh3, vhi + g1base + off);
                ldsm4(bl0, bl1, bl2, bl3, vlo + g1base + off);
                float* s0 = s[2 * jn];
                float* s1 = s[2 * jn + 1];
                mma16816(s0[0], s0[1], s0[2], s0[3], auh[kk][0], auh[kk][1], auh[kk][2], auh[kk][3], bh0, bh1);
                mma16816(s0[0], s0[1], s0[2], s0[3], auh[kk][0], auh[kk][1], auh[kk][2], auh[kk][3], bl0, bl1);
                mma16816(s0[0], s0[1], s0[2], s0[3], aul[kk][0], aul[kk][1], aul[kk][2], aul[kk][3], bh0, bh1);
                mma16816(s1[0], s1[1], s1[2], s1[3], auh[kk][0], auh[kk][1], auh[kk][2], auh[kk][3], bh2, bh3);
                mma16816(s1[0], s1[1], s1[2], s1[3], auh[kk][0], auh[kk][1], auh[kk][2], auh[kk][3], bl2, bl3);
                mma16816(s1[0], s1[1], s1[2], s1[3], aul[kk][0], aul[kk][1], aul[kk][2], aul[kk][3], bh2, bh3);
            }
        }

        // ---- GEMM2(t-1): num += P'(t-1) x V(t-1) (hi plane, buf (t-1)%3) ----
        if (t > 0) {
            const uint32_t vhp = sb + SM_VHI + ((t - 1) % 3) * ROWB;
            #pragma unroll
            for (int kk = 0; kk < 2; kk++) {
                const uint32_t ah0 = pA[2 * kk], ah1 = pB[2 * kk], ah2 = pA[2 * kk + 1], ah3 = pB[2 * kk + 1];
                #pragma unroll
                for (int jd = 0; jd < 4; jd++) {
                    const uint32_t off = kk * (16 * VSTR) + jd * 32;
                    uint32_t bh0, bh1, bh2, bh3;
                    ldsm4t(bh0, bh1, bh2, bh3, vhp + g2base + off);
                    float* n0 = num[2 * jd];
                    float* n1 = num[2 * jd + 1];
                    mma16816(n0[0], n0[1], n0[2], n0[3], ah0, ah1, ah2, ah3, bh0, bh1);
                    mma16816(n1[0], n1[1], n1[2], n1[3], ah0, ah1, ah2, ah3, bh2, bh3);
                }
            }
        }

        // ---- epilogue(t): mask, running max, branchless rescale, P'(t) ----
        float mt0 = 0.f, mt1 = 0.f;
        #pragma unroll
        for (int nt = 0; nt < 4; nt++) {
            s[nt][0] = (a0r[nt].x > 0) ? s[nt][0] : 0.f;
            s[nt][1] = (a0r[nt].y > 0) ? s[nt][1] : 0.f;
            s[nt][2] = (a1r[nt].x > 0) ? s[nt][2] : 0.f;
            s[nt][3] = (a1r[nt].y > 0) ? s[nt][3] : 0.f;
            mt0 = fmaxf(mt0, fmaxf(s[nt][0], s[nt][1]));
            mt1 = fmaxf(mt1, fmaxf(s[nt][2], s[nt][3]));
        }
        mt0 = fmaxf(mt0, __shfl_xor_sync(0xffffffffu, mt0, 1));
        mt0 = fmaxf(mt0, __shfl_xor_sync(0xffffffffu, mt0, 2));
        mt1 = fmaxf(mt1, __shfl_xor_sync(0xffffffffu, mt1, 1));
        mt1 = fmaxf(mt1, __shfl_xor_sync(0xffffffffu, mt1, 2));

        const float m0n = fmaxf(m0, mt0), m1n = fmaxf(m1, mt1);
        const float sc0 = __expf(m0 - m0n), sc1 = __expf(m1 - m1n);
        den0 *= sc0; den1 *= sc1;
        #pragma unroll
        for (int nd = 0; nd < 8; nd++) {
            num[nd][0] *= sc0; num[nd][1] *= sc0;
            num[nd][2] *= sc1; num[nd][3] *= sc1;
        }
        m0 = m0n; m1 = m1n;

        #pragma unroll
        for (int nt = 0; nt < 4; nt++) {
            float p00 = __expf(s[nt][0] - m0), p01 = __expf(s[nt][1] - m0);
            float p10 = __expf(s[nt][2] - m1), p11 = __expf(s[nt][3] - m1);
            den0 += p00 + p01;
            den1 += p10 + p11;
            pA[nt] = packh2(p00, p01);
            pB[nt] = packh2(p10, p11);
        }
        __syncthreads();                 // all reads of bufs done before next cp
    }

    // ---- drain: GEMM2(NTC-1) ----
    {
        const uint32_t vhp = sb + SM_VHI + ((NTC - 1) % 3) * ROWB;
        #pragma unroll
        for (int kk = 0; kk < 2; kk++) {
            const uint32_t ah0 = pA[2 * kk], ah1 = pB[2 * kk], ah2 = pA[2 * kk + 1], ah3 = pB[2 * kk + 1];
            #pragma unroll
            for (int jd = 0; jd < 4; jd++) {
                const uint32_t off = kk * (16 * VSTR) + jd * 32;
                uint32_t bh0, bh1, bh2, bh3;
                ldsm4t(bh0, bh1, bh2, bh3, vhp + g2base + off);
                float* n0 = num[2 * jd];
                float* n1 = num[2 * jd + 1];
                mma16816(n0[0], n0[1], n0[2], n0[3], ah0, ah1, ah2, ah3, bh0, bh1);
                mma16816(n1[0], n1[1], n1[2], n1[3], ah0, ah1, ah2, ah3, bh2, bh3);
            }
        }
    }
    __syncthreads();        // all V reads complete before aliasing smem

    // ---- end phase: merge (m, den, num) across item quarters; write partials ----
    float* dens = (float*)(smc + SM_DEN);          // [4][32]
    float* ms   = (float*)(smc + SM_DEN + 512);    // [4][32]
    float* numq = (float*)(smc + SM_NUMA);         // [4][32][68] fp32 (aliases V hi)

    if ((l & 3) == 0) { ms[q * 32 + r0] = m0; ms[q * 32 + r1] = m1; }
    __syncthreads();
    const float M0 = fmaxf(fmaxf(ms[r0], ms[32 + r0]), fmaxf(ms[64 + r0], ms[96 + r0]));
    const float M1 = fmaxf(fmaxf(ms[r1], ms[32 + r1]), fmaxf(ms[64 + r1], ms[96 + r1]));
    const float f0 = __expf(m0 - M0), f1 = __expf(m1 - M1);

    #pragma unroll
    for (int nd = 0; nd < 8; nd++) {
        *(float2*)(numq + q * (32 * 68) + r0 * 68 + 8 * nd + cb) =
            make_float2(num[nd][0] * f0, num[nd][1] * f0);
        *(float2*)(numq + q * (32 * 68) + r1 * 68 + 8 * nd + cb) =
            make_float2(num[nd][2] * f1, num[nd][3] * f1);
    }
    den0 += __shfl_xor_sync(0xffffffffu, den0, 1);
    den0 += __shfl_xor_sync(0xffffffffu, den0, 2);
    den1 += __shfl_xor_sync(0xffffffffu, den1, 1);
    den1 += __shfl_xor_sync(0xffffffffu, den1, 2);
    if ((l & 3) == 0) { dens[q * 32 + r0] = den0 * f0; dens[q * 32 + r1] = den1 * f1; }
    __syncthreads();

    // reduce num across q and write partial numerator to gmem
    {
        const int row = tid >> 3, c0 = (tid & 7) * 8;
        float acc[8];
        #pragma unroll
        for (int j = 0; j < 8; j++) acc[j] = numq[row * 68 + c0 + j];
        #pragma unroll
        for (int qq = 1; qq < 4; qq++)
            #pragma unroll
            for (int j = 0; j < 8; j++)
                acc[j] += numq[qq * (32 * 68) + row * 68 + c0 + j];
        *(float4*)&g_pnum[bid][row][c0]     = make_float4(acc[0], acc[1], acc[2], acc[3]);
        *(float4*)&g_pnum[bid][row][c0 + 4] = make_float4(acc[4], acc[5], acc[6], acc[7]);
    }
    if (tid < 32) {
        g_pden[bid][tid] = dens[tid] + dens[32 + tid] + dens[64 + tid] + dens[96 + tid];
        g_pm[bid][tid]   = fmaxf(fmaxf(ms[tid], ms[32 + tid]), fmaxf(ms[64 + tid], ms[96 + tid]));
    }
}

// ---- merge the NCH item-chunk partials per u-block, normalize, apply W ----
__global__ void __launch_bounds__(256)
merge_kernel(const float* __restrict__ Wmat, float* __restrict__ out)
{
    __shared__ float Ws[4096];
    __shared__ float amg[BM * 68];
    __shared__ float dinvs[BM];
    const int tid = threadIdx.x;
    const int ub  = blockIdx.x;                 // one u-block (32 users)
    const int base = ub * 4;

    #pragma unroll
    for (int j = 0; j < 16; j++) Ws[tid + 256 * j] = Wmat[tid + 256 * j];

    const int row = tid >> 3, c0 = (tid & 7) * 8;

    // global max + weights per row (redundant across the 8 threads of a row; cheap)
    const float mm0 = g_pm[base + 0][row], mm1 = g_pm[base + 1][row];
    const float mm2 = g_pm[base + 2][row], mm3 = g_pm[base + 3][row];
    const float Mg  = fmaxf(fmaxf(mm0, mm1), fmaxf(mm2, mm3));
    const float w0 = __expf(mm0 - Mg), w1 = __expf(mm1 - Mg);
    const float w2 = __expf(mm2 - Mg), w3 = __expf(mm3 - Mg);

    if ((tid & 7) == 0) {
        const float den = w0 * g_pden[base + 0][row] + w1 * g_pden[base + 1][row]
                        + w2 * g_pden[base + 2][row] + w3 * g_pden[base + 3][row];
        dinvs[row] = 1.0f / den;
    }

    float acc[8];
    {
        const float4* n0 = (const float4*)&g_pnum[base + 0][row][c0];
        const float4* n1 = (const float4*)&g_pnum[base + 1][row][c0];
        const float4* n2 = (const float4*)&g_pnum[base + 2][row][c0];
        const float4* n3 = (const float4*)&g_pnum[base + 3][row][c0];
        #pragma unroll
        for (int h = 0; h < 2; h++) {
            float4 a0 = n0[h], a1 = n1[h], a2 = n2[h], a3 = n3[h];
            acc[4*h + 0] = w0 * a0.x + w1 * a1.x + w2 * a2.x + w3 * a3.x;
            acc[4*h + 1] = w0 * a0.y + w1 * a1.y + w2 * a2.y + w3 * a3.y;
            acc[4*h + 2] = w0 * a0.z + w1 * a1.z + w2 * a2.z + w3 * a3.z;
            acc[4*h + 3] = w0 * a0.w + w1 * a1.w + w2 * a2.w + w3 * a3.w;
        }
    }
    #pragma unroll
    for (int j = 0; j < 8; j++) amg[row * 68 + c0 + j] = acc[j];
    __syncthreads();

    // GEMM3: out = (num/den) @ W
    const float dinv = dinvs[row];
    float o[8] = {};
    #pragma unroll 8
    for (int k = 0; k < 64; k++) {
        const float a = amg[row * 68 + k];
        const float4 wv0 = *(const float4*)(Ws + k * 64 + c0);
        const float4 wv1 = *(const float4*)(Ws + k * 64 + c0 + 4);
        o[0] = fmaf(a, wv0.x, o[0]); o[1] = fmaf(a, wv0.y, o[1]);
        o[2] = fmaf(a, wv0.z, o[2]); o[3] = fmaf(a, wv0.w, o[3]);
        o[4] = fmaf(a, wv1.x, o[4]); o[5] = fmaf(a, wv1.y, o[5]);
        o[6] = fmaf(a, wv1.z, o[6]); o[7] = fmaf(a, wv1.w, o[7]);
    }
    float4* op = (float4*)(out + (long)(ub * BM + row) * OUT_DIM + c0);
    op[0] = make_float4(o[0] * dinv, o[1] * dinv, o[2] * dinv, o[3] * dinv);
    op[1] = make_float4(o[4] * dinv, o[5] * dinv, o[6] * dinv, o[7] * dinv);
}

extern "C" void kernel_launch(void* const* d_in, const int* in_sizes, int n_in,
                              void* d_out, int out_size)
{
    const float* user_emb = (const float*)d_in[0];
    const float* item_emb = (const float*)d_in[1];
    const float* Wmat     = (const float*)d_in[2];
    const int*   adj      = (const int*)d_in[3];
    float*       out      = (float*)d_out;

    vsplit_kernel<<<I_DIM * D_DIM / 8 / 256, 256>>>(item_emb);
    cudaFuncSetAttribute(atten_hmma_kernel,
                         cudaFuncAttributeMaxDynamicSharedMemorySize, SMEM_TOTAL);
    atten_hmma_kernel<<<(U_DIM / BM) * NCH, 256, SMEM_TOTAL>>>(user_emb, adj);
    merge_kernel<<<U_DIM / BM, 256>>>(Wmat, out);
}

// round 12
// speedup vs baseline: 1.0619x; 1.0130x over previous
#include <cuda_runtime.h>
#include <cuda_fp16.h>
#include <cstdint>

// AttenConv round 11: fp16 HMMA flash kernel, SINGLE barrier per tile.
// out[u,:] = softmax_i(adj?<U_u,V_i>:0) @ V @ W
// GEMM1: fp16 hi/lo 3-term; GEMM2: single fp16 term (p' <= 1), inline.
// Round 11: 3 smem buffers per V plane + only one __syncthreads per tile
// (after cp.async wait). Warps may spread across a full iteration, so one
// warp's epilogue overlaps another's MMA stream. U staging area aliases
// hibuf[2] (first written at iter 1, after all pre-loop U ldsm complete).

#define U_DIM   8192
#define I_DIM   16384
#define D_DIM   64
#define OUT_DIM 64
#define BM      32          // users per CTA
#define BN      128         // items per tile
#define NCH     4           // item chunks (CTAs per u-block)
#define NTC     32          // tiles per CTA
#define VSTR    144         // bytes per 64-half row
#define ROWB    18432       // 128 rows * 144B = one tile plane

// smem layout
#define SM_VHI  0                    // hi plane x3: [0, 55296)
#define SM_VLO  55296                // lo plane x3: [55296, 110592)
#define SM_DEN  110592               // dens[4][32] 512 + ms[4][32] 512
#define SM_U_HI (SM_VHI + 2*ROWB)    // U hi [32][72] inside hibuf[2]
#define SM_U_LO (SM_U_HI + 4608)     // U lo [32][72] inside hibuf[2]
#define SM_NUMA 0                    // end-phase alias: num [4][32][68] fp32
#define SMEM_TOTAL 111616

__device__ __align__(16) __half g_vhi[I_DIM][72];
__device__ __align__(16) __half g_vlo[I_DIM][72];
__device__ __align__(16) float  g_pnum[1024][BM][D_DIM];
__device__ float g_pden[1024][BM];
__device__ float g_pm[1024][BM];

__device__ __forceinline__ uint32_t smem_u32(const void* p) {
    uint32_t a;
    asm("{ .reg .u64 t; cvta.to.shared.u64 t, %1; cvt.u32.u64 %0, t; }" : "=r"(a) : "l"(p));
    return a;
}
__device__ __forceinline__ void cp16(uint32_t dst, const void* src) {
    asm volatile("cp.async.cg.shared.global [%0], [%1], 16;" :: "r"(dst), "l"(src));
}
#define CP_COMMIT() asm volatile("cp.async.commit_group;" ::: "memory")
#define CP_WAIT1()  asm volatile("cp.async.wait_group 1;" ::: "memory")

__device__ __forceinline__ void mma16816(float& d0, float& d1, float& d2, float& d3,
                                         uint32_t a0, uint32_t a1, uint32_t a2, uint32_t a3,
                                         uint32_t b0, uint32_t b1) {
    asm volatile("mma.sync.aligned.m16n8k16.row.col.f32.f16.f16.f32 "
                 "{%0,%1,%2,%3},{%4,%5,%6,%7},{%8,%9},{%0,%1,%2,%3};"
                 : "+f"(d0), "+f"(d1), "+f"(d2), "+f"(d3)
                 : "r"(a0), "r"(a1), "r"(a2), "r"(a3), "r"(b0), "r"(b1));
}
__device__ __forceinline__ void ldsm4(uint32_t& r0, uint32_t& r1, uint32_t& r2, uint32_t& r3,
                                      uint32_t addr) {
    asm volatile("ldmatrix.sync.aligned.m8n8.x4.shared.b16 {%0,%1,%2,%3}, [%4];"
                 : "=r"(r0), "=r"(r1), "=r"(r2), "=r"(r3) : "r"(addr));
}
__device__ __forceinline__ void ldsm4t(uint32_t& r0, uint32_t& r1, uint32_t& r2, uint32_t& r3,
                                       uint32_t addr) {
    asm volatile("ldmatrix.sync.aligned.m8n8.x4.trans.shared.b16 {%0,%1,%2,%3}, [%4];"
                 : "=r"(r0), "=r"(r1), "=r"(r2), "=r"(r3) : "r"(addr));
}
__device__ __forceinline__ uint32_t packh2(float x0, float x1) {
    uint32_t r;
    asm("cvt.rn.f16x2.f32 %0, %1, %2;" : "=r"(r) : "f"(x1), "f"(x0));
    return r;
}
__device__ __forceinline__ void split2h(float x0, float x1, uint32_t& h, uint32_t& l) {
    h = packh2(x0, x1);
    __half2 hv = *(__half2*)&h;
    float2 back = __half22float2(hv);
    l = packh2(x0 - back.x, x1 - back.y);
}

// ---- precompute: split item_emb into fp16 hi/lo planes with VSTR padding ----
__global__ void __launch_bounds__(256)
vsplit_kernel(const float* __restrict__ item_emb)
{
    const int gid  = blockIdx.x * 256 + threadIdx.x;
    const int item = gid >> 3;
    const int d0   = (gid & 7) * 8;
    const float4* vp = (const float4*)(item_emb + (long)item * D_DIM + d0);
    const float4 v0 = vp[0], v1 = vp[1];
    uint32_t h0, l0, h1, l1, h2, l2, h3, l3;
    split2h(v0.x, v0.y, h0, l0); split2h(v0.z, v0.w, h1, l1);
    split2h(v1.x, v1.y, h2, l2); split2h(v1.z, v1.w, h3, l3);
    *(uint4*)&g_vhi[item][d0] = make_uint4(h0, h1, h2, h3);
    *(uint4*)&g_vlo[item][d0] = make_uint4(l0, l1, l2, l3);
}

__global__ void __launch_bounds__(256, 2)
atten_hmma_kernel(const float* __restrict__ user_emb,
                  const int*   __restrict__ adj)
{
    extern __shared__ __align__(128) char smc[];
    const uint32_t sb = smem_u32(smc);
    const int tid = threadIdx.x;
    const int bid = blockIdx.x;
    const int ub  = bid >> 2;       // u-block
    const int ch  = bid & 3;        // item chunk
    const int w   = tid >> 5;
    const int l   = tid & 31;
    const int m   = w & 1;          // user group: rows 16m..16m+15
    const int q   = w >> 1;         // item quarter within tile
    const int u0  = ub * BM;
    const int tg0 = ch * NTC;       // first global tile index

    const char* vhib = (const char*)g_vhi;
    const char* vlob = (const char*)g_vlo;

    // ---- prologue: stage U hi/lo (inside hibuf[2]); cp.async tile 0 ----
    {
        const int row = tid >> 3, d0 = (tid & 7) * 8;
        const float4* up = (const float4*)(user_emb + (long)(u0 + row) * D_DIM + d0);
        const float4 v0 = up[0], v1 = up[1];
        uint32_t h0, l0h, h1, l1h, h2, l2h, h3, l3h;
        split2h(v0.x, v0.y, h0, l0h); split2h(v0.z, v0.w, h1, l1h);
        split2h(v1.x, v1.y, h2, l2h); split2h(v1.z, v1.w, h3, l3h);
        *(uint4*)(smc + SM_U_HI + row * VSTR + d0 * 2) = make_uint4(h0, h1, h2, h3);
        *(uint4*)(smc + SM_U_LO + row * VSTR + d0 * 2) = make_uint4(l0h, l1h, l2h, l3h);
    }
    {
        const long srcoff = (long)tg0 * ROWB;
        for (int idx = tid; idx < 1152; idx += 256) {
            cp16(sb + SM_VHI + idx * 16, vhib + srcoff + idx * 16);
            cp16(sb + SM_VLO + idx * 16, vlob + srcoff + idx * 16);
        }
    }
    CP_COMMIT();
    __syncthreads();

    // ---- persistent U A-fragments (hi/lo fp16); done BEFORE iter 1's cp
    //      can clobber hibuf[2] (ordered by the iter-0 barrier) ----
    uint32_t auh[4][4], aul[4][4];
    {
        const uint32_t abase = (16 * m + (l & 15)) * VSTR + (l >> 4) * 16;
        #pragma unroll
        for (int kk = 0; kk < 4; kk++) {
            ldsm4(auh[kk][0], auh[kk][1], auh[kk][2], auh[kk][3], sb + SM_U_HI + abase + kk * 32);
            ldsm4(aul[kk][0], aul[kk][1], aul[kk][2], aul[kk][3], sb + SM_U_LO + abase + kk * 32);
        }
    }

    // ldmatrix lane bases within a V plane (quarter q)
    const uint32_t g1base = (32 * q + (l & 7) + (l >> 4) * 8) * VSTR + (((l >> 3) & 1) * 8) * 2;
    const uint32_t g2base = (32 * q + (l & 7) + ((l >> 3) & 1) * 8) * VSTR + (l >> 4) * 16;

    float num[8][4] = {};
    float den0 = 0.f, den1 = 0.f;
    float m0 = 0.f, m1 = 0.f;

    const int r0 = 16 * m + (l >> 2), r1 = r0 + 8;
    const int cb = 2 * (l & 3);
    const long adjr0 = (long)(u0 + r0) * I_DIM + 32 * q + cb + (long)tg0 * BN;
    const long adjr1 = adjr0 + 8L * I_DIM;

    int bcur = 0;                    // buffer index t % 3

    #pragma unroll 1
    for (int t = 0; t < NTC; t++) {
        const int bnext = (bcur == 2) ? 0 : bcur + 1;

        // stage tile t+1 into buf bnext (1-ahead)
        if (t + 1 < NTC) {
            const long srcoff = (long)(tg0 + t + 1) * ROWB;
            const uint32_t dh = sb + SM_VHI + bnext * ROWB;
            const uint32_t dl = sb + SM_VLO + bnext * ROWB;
            for (int idx = tid; idx < 1152; idx += 256) {
                cp16(dh + idx * 16, vhib + srcoff + idx * 16);
                cp16(dl + idx * 16, vlob + srcoff + idx * 16);
            }
        }
        CP_COMMIT();

        // adj for this tile (overlaps the wait)
        int2 a0r[4], a1r[4];
        {
            const int2* p0 = (const int2*)(adj + adjr0 + (long)t * BN);
            const int2* p1 = (const int2*)(adj + adjr1 + (long)t * BN);
            #pragma unroll
            for (int nt = 0; nt < 4; nt++) { a0r[nt] = p0[4 * nt]; a1r[nt] = p1[4 * nt]; }
        }

        CP_WAIT1();
        __syncthreads();                 // THE one barrier per tile

        const uint32_t vhi = sb + SM_VHI + bcur * ROWB;
        const uint32_t vlo = sb + SM_VLO + bcur * ROWB;

        // ---- GEMM1(t): S[16 x 32] = U x V^T (3-term fp16 split) ----
        float s[4][4] = {};
        #pragma unroll
        for (int kk = 0; kk < 4; kk++) {
            #pragma unroll
            for (int jn = 0; jn < 2; jn++) {
                const uint32_t off = jn * (16 * VSTR) + kk * 32;
                uint32_t bh0, bh1, bh2, bh3, bl0, bl1, bl2, bl3;
                ldsm4(bh0, bh1, bh2, bh3, vhi + g1base + off);
                ldsm4(bl0, bl1, bl2, bl3, vlo + g1base + off);
                float* s0 = s[2 * jn];
                float* s1 = s[2 * jn + 1];
                mma16816(s0[0], s0[1], s0[2], s0[3], auh[kk][0], auh[kk][1], auh[kk][2], auh[kk][3], bh0, bh1);
                mma16816(s0[0], s0[1], s0[2], s0[3], auh[kk][0], auh[kk][1], auh[kk][2], auh[kk][3], bl0, bl1);
                mma16816(s0[0], s0[1], s0[2], s0[3], aul[kk][0], aul[kk][1], aul[kk][2], aul[kk][3], bh0, bh1);
                mma16816(s1[0], s1[1], s1[2], s1[3], auh[kk][0], auh[kk][1], auh[kk][2], auh[kk][3], bh2, bh3);
                mma16816(s1[0], s1[1], s1[2], s1[3], auh[kk][0], auh[kk][1], auh[kk][2], auh[kk][3], bl2, bl3);
                mma16816(s1[0], s1[1], s1[2], s1[3], aul[kk][0], aul[kk][1], aul[kk][2], aul[kk][3], bh2, bh3);
            }
        }

        // ---- epilogue(t): mask, running max, branchless rescale, P'(t) ----
        float mt0 = 0.f, mt1 = 0.f;
        #pragma unroll
        for (int nt = 0; nt < 4; nt++) {
            s[nt][0] = (a0r[nt].x > 0) ? s[nt][0] : 0.f;
            s[nt][1] = (a0r[nt].y > 0) ? s[nt][1] : 0.f;
            s[nt][2] = (a1r[nt].x > 0) ? s[nt][2] : 0.f;
            s[nt][3] = (a1r[nt].y > 0) ? s[nt][3] : 0.f;
            mt0 = fmaxf(mt0, fmaxf(s[nt][0], s[nt][1]));
            mt1 = fmaxf(mt1, fmaxf(s[nt][2], s[nt][3]));
        }
        mt0 = fmaxf(mt0, __shfl_xor_sync(0xffffffffu, mt0, 1));
        mt0 = fmaxf(mt0, __shfl_xor_sync(0xffffffffu, mt0, 2));
        mt1 = fmaxf(mt1, __shfl_xor_sync(0xffffffffu, mt1, 1));
        mt1 = fmaxf(mt1, __shfl_xor_sync(0xffffffffu, mt1, 2));

        const float m0n = fmaxf(m0, mt0), m1n = fmaxf(m1, mt1);
        const float sc0 = __expf(m0 - m0n), sc1 = __expf(m1 - m1n);
        den0 *= sc0; den1 *= sc1;
        #pragma unroll
        for (int nd = 0; nd < 8; nd++) {
            num[nd][0] *= sc0; num[nd][1] *= sc0;
            num[nd][2] *= sc1; num[nd][3] *= sc1;
        }
        m0 = m0n; m1 = m1n;

        uint32_t pA[4], pB[4];
        #pragma unroll
        for (int nt = 0; nt < 4; nt++) {
            float p00 = __expf(s[nt][0] - m0), p01 = __expf(s[nt][1] - m0);
            float p10 = __expf(s[nt][2] - m1), p11 = __expf(s[nt][3] - m1);
            den0 += p00 + p01;
            den1 += p10 + p11;
            pA[nt] = packh2(p00, p01);
            pB[nt] = packh2(p10, p11);
        }

        // ---- GEMM2(t): num += P'(t) x V(t) (hi plane, inline) ----
        #pragma unroll
        for (int kk = 0; kk < 2; kk++) {
            const uint32_t ah0 = pA[2 * kk], ah1 = pB[2 * kk], ah2 = pA[2 * kk + 1], ah3 = pB[2 * kk + 1];
            #pragma unroll
            for (int jd = 0; jd < 4; jd++) {
                const uint32_t off = kk * (16 * VSTR) + jd * 32;
                uint32_t bh0, bh1, bh2, bh3;
                ldsm4t(bh0, bh1, bh2, bh3, vhi + g2base + off);
                float* n0 = num[2 * jd];
                float* n1 = num[2 * jd + 1];
                mma16816(n0[0], n0[1], n0[2], n0[3], ah0, ah1, ah2, ah3, bh0, bh1);
                mma16816(n1[0], n1[1], n1[2], n1[3], ah0, ah1, ah2, ah3, bh2, bh3);
            }
        }
        // NO end-of-loop sync: 3 buffers make one-iteration warp skew safe.
        bcur = bnext;
    }
    __syncthreads();        // all V reads complete before aliasing smem

    // ---- end phase: merge (m, den, num) across item quarters; write partials ----
    float* dens = (float*)(smc + SM_DEN);          // [4][32]
    float* ms   = (float*)(smc + SM_DEN + 512);    // [4][32]
    float* numq = (float*)(smc + SM_NUMA);         // [4][32][68] fp32 (aliases V)

    if ((l & 3) == 0) { ms[q * 32 + r0] = m0; ms[q * 32 + r1] = m1; }
    __syncthreads();
    const float M0 = fmaxf(fmaxf(ms[r0], ms[32 + r0]), fmaxf(ms[64 + r0], ms[96 + r0]));
    const float M1 = fmaxf(fmaxf(ms[r1], ms[32 + r1]), fmaxf(ms[64 + r1], ms[96 + r1]));
    const float f0 = __expf(m0 - M0), f1 = __expf(m1 - M1);

    #pragma unroll
    for (int nd = 0; nd < 8; nd++) {
        *(float2*)(numq + q * (32 * 68) + r0 * 68 + 8 * nd + cb) =
            make_float2(num[nd][0] * f0, num[nd][1] * f0);
        *(float2*)(numq + q * (32 * 68) + r1 * 68 + 8 * nd + cb) =
            make_float2(num[nd][2] * f1, num[nd][3] * f1);
    }
    den0 += __shfl_xor_sync(0xffffffffu, den0, 1);
    den0 += __shfl_xor_sync(0xffffffffu, den0, 2);
    den1 += __shfl_xor_sync(0xffffffffu, den1, 1);
    den1 += __shfl_xor_sync(0xffffffffu, den1, 2);
    if ((l & 3) == 0) { dens[q * 32 + r0] = den0 * f0; dens[q * 32 + r1] = den1 * f1; }
    __syncthreads();

    // reduce num across q and write partial numerator to gmem
    {
        const int row = tid >> 3, c0 = (tid & 7) * 8;
        float acc[8];
        #pragma unroll
        for (int j = 0; j < 8; j++) acc[j] = numq[row * 68 + c0 + j];
        #pragma unroll
        for (int qq = 1; qq < 4; qq++)
            #pragma unroll
            for (int j = 0; j < 8; j++)
                acc[j] += numq[qq * (32 * 68) + row * 68 + c0 + j];
        *(float4*)&g_pnum[bid][row][c0]     = make_float4(acc[0], acc[1], acc[2], acc[3]);
        *(float4*)&g_pnum[bid][row][c0 + 4] = make_float4(acc[4], acc[5], acc[6], acc[7]);
    }
    if (tid < 32) {
        g_pden[bid][tid] = dens[tid] + dens[32 + tid] + dens[64 + tid] + dens[96 + tid];
        g_pm[bid][tid]   = fmaxf(fmaxf(ms[tid], ms[32 + tid]), fmaxf(ms[64 + tid], ms[96 + tid]));
    }
}

// ---- merge the NCH item-chunk partials per u-block, normalize, apply W ----
__global__ void __launch_bounds__(256)
merge_kernel(const float* __restrict__ Wmat, float* __restrict__ out)
{
    __shared__ float Ws[4096];
    __shared__ float amg[BM * 68];
    __shared__ float dinvs[BM];
    const int tid = threadIdx.x;
    const int ub  = blockIdx.x;
    const int base = ub * 4;

    #pragma unroll
    for (int j = 0; j < 16; j++) Ws[tid + 256 * j] = Wmat[tid + 256 * j];

    const int row = tid >> 3, c0 = (tid & 7) * 8;

    const float mm0 = g_pm[base + 0][row], mm1 = g_pm[base + 1][row];
    const float mm2 = g_pm[base + 2][row], mm3 = g_pm[base + 3][row];
    const float Mg  = fmaxf(fmaxf(mm0, mm1), fmaxf(mm2, mm3));
    const float w0 = __expf(mm0 - Mg), w1 = __expf(mm1 - Mg);
    const float w2 = __expf(mm2 - Mg), w3 = __expf(mm3 - Mg);

    if ((tid & 7) == 0) {
        const float den = w0 * g_pden[base + 0][row] + w1 * g_pden[base + 1][row]
                        + w2 * g_pden[base + 2][row] + w3 * g_pden[base + 3][row];
        dinvs[row] = 1.0f / den;
    }

    float acc[8];
    {
        const float4* n0 = (const float4*)&g_pnum[base + 0][row][c0];
        const float4* n1 = (const float4*)&g_pnum[base + 1][row][c0];
        const float4* n2 = (const float4*)&g_pnum[base + 2][row][c0];
        const float4* n3 = (const float4*)&g_pnum[base + 3][row][c0];
        #pragma unroll
        for (int h = 0; h < 2; h++) {
            float4 a0 = n0[h], a1 = n1[h], a2 = n2[h], a3 = n3[h];
            acc[4*h + 0] = w0 * a0.x + w1 * a1.x + w2 * a2.x + w3 * a3.x;
            acc[4*h + 1] = w0 * a0.y + w1 * a1.y + w2 * a2.y + w3 * a3.y;
            acc[4*h + 2] = w0 * a0.z + w1 * a1.z + w2 * a2.z + w3 * a3.z;
            acc[4*h + 3] = w0 * a0.w + w1 * a1.w + w2 * a2.w + w3 * a3.w;
        }
    }
    #pragma unroll
    for (int j = 0; j < 8; j++) amg[row * 68 + c0 + j] = acc[j];
    __syncthreads();

    const float dinv = dinvs[row];
    float o[8] = {};
    #pragma unroll 8
    for (int k = 0; k < 64; k++) {
        const float a = amg[row * 68 + k];
        const float4 wv0 = *(const float4*)(Ws + k * 64 + c0);
        const float4 wv1 = *(const float4*)(Ws + k * 64 + c0 + 4);
        o[0] = fmaf(a, wv0.x, o[0]); o[1] = fmaf(a, wv0.y, o[1]);
        o[2] = fmaf(a, wv0.z, o[2]); o[3] = fmaf(a, wv0.w, o[3]);
        o[4] = fmaf(a, wv1.x, o[4]); o[5] = fmaf(a, wv1.y, o[5]);
        o[6] = fmaf(a, wv1.z, o[6]); o[7] = fmaf(a, wv1.w, o[7]);
    }
    float4* op = (float4*)(out + (long)(ub * BM + row) * OUT_DIM + c0);
    op[0] = make_float4(o[0] * dinv, o[1] * dinv, o[2] * dinv, o[3] * dinv);
    op[1] = make_float4(o[4] * dinv, o[5] * dinv, o[6] * dinv, o[7] * dinv);
}

extern "C" void kernel_launch(void* const* d_in, const int* in_sizes, int n_in,
                              void* d_out, int out_size)
{
    const float* user_emb = (const float*)d_in[0];
    const float* item_emb = (const float*)d_in[1];
    const float* Wmat     = (const float*)d_in[2];
    const int*   adj      = (const int*)d_in[3];
    float*       out      = (float*)d_out;

    vsplit_kernel<<<I_DIM * D_DIM / 8 / 256, 256>>>(item_emb);
    cudaFuncSetAttribute(atten_hmma_kernel,
                         cudaFuncAttributeMaxDynamicSharedMemorySize, SMEM_TOTAL);
    atten_hmma_kernel<<<(U_DIM / BM) * NCH, 256, SMEM_TOTAL>>>(user_emb, adj);
    merge_kernel<<<U_DIM / BM, 256>>>(Wmat, out);
}

// round 13
// speedup vs baseline: 1.1476x; 1.0807x over previous
#include <cuda_runtime.h>
#include <cuda_fp16.h>
#include <cstdint>

// AttenConv round 12: fp16 HMMA flash kernel — MMA scheduling unlock.
// out[u,:] = softmax_i(adj?<U_u,V_i>:0) @ V @ W
// GEMM1: fp16 hi/lo 3-term; GEMM2: single fp16 term (p' <= 1), inline.
// Round 12 changes vs round 11 (structure otherwise identical):
//  (1) mma asm is NON-volatile -> ptxas may schedule/interleave MMAs.
//  (2) GEMM1 issues MMAs round-robin across the 4 accumulators instead of
//      3 back-to-back dependent MMAs into the same accumulator.

#define U_DIM   8192
#define I_DIM   16384
#define D_DIM   64
#define OUT_DIM 64
#define BM      32          // users per CTA
#define BN      128         // items per tile
#define NCH     4           // item chunks (CTAs per u-block)
#define NTC     32          // tiles per CTA
#define VSTR    144         // bytes per 64-half row
#define ROWB    18432       // 128 rows * 144B = one tile plane

// smem layout
#define SM_VHI  0                    // hi plane x3: [0, 55296)
#define SM_VLO  55296                // lo plane x3: [55296, 110592)
#define SM_DEN  110592               // dens[4][32] 512 + ms[4][32] 512
#define SM_U_HI (SM_VHI + 2*ROWB)    // U hi [32][72] inside hibuf[2]
#define SM_U_LO (SM_U_HI + 4608)     // U lo [32][72] inside hibuf[2]
#define SM_NUMA 0                    // end-phase alias: num [4][32][68] fp32
#define SMEM_TOTAL 111616

__device__ __align__(16) __half g_vhi[I_DIM][72];
__device__ __align__(16) __half g_vlo[I_DIM][72];
__device__ __align__(16) float  g_pnum[1024][BM][D_DIM];
__device__ float g_pden[1024][BM];
__device__ float g_pm[1024][BM];

__device__ __forceinline__ uint32_t smem_u32(const void* p) {
    uint32_t a;
    asm("{ .reg .u64 t; cvta.to.shared.u64 t, %1; cvt.u32.u64 %0, t; }" : "=r"(a) : "l"(p));
    return a;
}
__device__ __forceinline__ void cp16(uint32_t dst, const void* src) {
    asm volatile("cp.async.cg.shared.global [%0], [%1], 16;" :: "r"(dst), "l"(src));
}
#define CP_COMMIT() asm volatile("cp.async.commit_group;" ::: "memory")
#define CP_WAIT1()  asm volatile("cp.async.wait_group 1;" ::: "memory")

// NON-volatile: pure register op, lets ptxas schedule MMAs freely.
__device__ __forceinline__ void mma16816(float* d,
                                         const uint32_t* a,
                                         uint32_t b0, uint32_t b1) {
    asm("mma.sync.aligned.m16n8k16.row.col.f32.f16.f16.f32 "
        "{%0,%1,%2,%3},{%4,%5,%6,%7},{%8,%9},{%0,%1,%2,%3};"
        : "+f"(d[0]), "+f"(d[1]), "+f"(d[2]), "+f"(d[3])
        : "r"(a[0]), "r"(a[1]), "r"(a[2]), "r"(a[3]), "r"(b0), "r"(b1));
}
__device__ __forceinline__ void mma16816v(float* d,
                                          uint32_t a0, uint32_t a1, uint32_t a2, uint32_t a3,
                                          uint32_t b0, uint32_t b1) {
    asm("mma.sync.aligned.m16n8k16.row.col.f32.f16.f16.f32 "
        "{%0,%1,%2,%3},{%4,%5,%6,%7},{%8,%9},{%0,%1,%2,%3};"
        : "+f"(d[0]), "+f"(d[1]), "+f"(d[2]), "+f"(d[3])
        : "r"(a0), "r"(a1), "r"(a2), "r"(a3), "r"(b0), "r"(b1));
}
__device__ __forceinline__ void ldsm4(uint32_t* r, uint32_t addr) {
    asm volatile("ldmatrix.sync.aligned.m8n8.x4.shared.b16 {%0,%1,%2,%3}, [%4];"
                 : "=r"(r[0]), "=r"(r[1]), "=r"(r[2]), "=r"(r[3]) : "r"(addr));
}
__device__ __forceinline__ void ldsm4t(uint32_t& r0, uint32_t& r1, uint32_t& r2, uint32_t& r3,
                                       uint32_t addr) {
    asm volatile("ldmatrix.sync.aligned.m8n8.x4.trans.shared.b16 {%0,%1,%2,%3}, [%4];"
                 : "=r"(r0), "=r"(r1), "=r"(r2), "=r"(r3) : "r"(addr));
}
__device__ __forceinline__ uint32_t packh2(float x0, float x1) {
    uint32_t r;
    asm("cvt.rn.f16x2.f32 %0, %1, %2;" : "=r"(r) : "f"(x1), "f"(x0));
    return r;
}
__device__ __forceinline__ void split2h(float x0, float x1, uint32_t& h, uint32_t& l) {
    h = packh2(x0, x1);
    __half2 hv = *(__half2*)&h;
    float2 back = __half22float2(hv);
    l = packh2(x0 - back.x, x1 - back.y);
}

// ---- precompute: split item_emb into fp16 hi/lo planes with VSTR padding ----
__global__ void __launch_bounds__(256)
vsplit_kernel(const float* __restrict__ item_emb)
{
    const int gid  = blockIdx.x * 256 + threadIdx.x;
    const int item = gid >> 3;
    const int d0   = (gid & 7) * 8;
    const float4* vp = (const float4*)(item_emb + (long)item * D_DIM + d0);
    const float4 v0 = vp[0], v1 = vp[1];
    uint32_t h0, l0, h1, l1, h2, l2, h3, l3;
    split2h(v0.x, v0.y, h0, l0); split2h(v0.z, v0.w, h1, l1);
    split2h(v1.x, v1.y, h2, l2); split2h(v1.z, v1.w, h3, l3);
    *(uint4*)&g_vhi[item][d0] = make_uint4(h0, h1, h2, h3);
    *(uint4*)&g_vlo[item][d0] = make_uint4(l0, l1, l2, l3);
}

__global__ void __launch_bounds__(256, 2)
atten_hmma_kernel(const float* __restrict__ user_emb,
                  const int*   __restrict__ adj)
{
    extern __shared__ __align__(128) char smc[];
    const uint32_t sb = smem_u32(smc);
    const int tid = threadIdx.x;
    const int bid = blockIdx.x;
    const int ub  = bid >> 2;       // u-block
    const int ch  = bid & 3;        // item chunk
    const int w   = tid >> 5;
    const int l   = tid & 31;
    const int m   = w & 1;          // user group: rows 16m..16m+15
    const int q   = w >> 1;         // item quarter within tile
    const int u0  = ub * BM;
    const int tg0 = ch * NTC;       // first global tile index

    const char* vhib = (const char*)g_vhi;
    const char* vlob = (const char*)g_vlo;

    // ---- prologue: stage U hi/lo (inside hibuf[2]); cp.async tile 0 ----
    {
        const int row = tid >> 3, d0 = (tid & 7) * 8;
        const float4* up = (const float4*)(user_emb + (long)(u0 + row) * D_DIM + d0);
        const float4 v0 = up[0], v1 = up[1];
        uint32_t h0, l0h, h1, l1h, h2, l2h, h3, l3h;
        split2h(v0.x, v0.y, h0, l0h); split2h(v0.z, v0.w, h1, l1h);
        split2h(v1.x, v1.y, h2, l2h); split2h(v1.z, v1.w, h3, l3h);
        *(uint4*)(smc + SM_U_HI + row * VSTR + d0 * 2) = make_uint4(h0, h1, h2, h3);
        *(uint4*)(smc + SM_U_LO + row * VSTR + d0 * 2) = make_uint4(l0h, l1h, l2h, l3h);
    }
    {
        const long srcoff = (long)tg0 * ROWB;
        for (int idx = tid; idx < 1152; idx += 256) {
            cp16(sb + SM_VHI + idx * 16, vhib + srcoff + idx * 16);
            cp16(sb + SM_VLO + idx * 16, vlob + srcoff + idx * 16);
        }
    }
    CP_COMMIT();
    __syncthreads();

    // ---- persistent U A-fragments (hi/lo fp16) ----
    uint32_t auh[4][4], aul[4][4];
    {
        const uint32_t abase = (16 * m + (l & 15)) * VSTR + (l >> 4) * 16;
        #pragma unroll
        for (int kk = 0; kk < 4; kk++) {
            ldsm4(auh[kk], sb + SM_U_HI + abase + kk * 32);
            ldsm4(aul[kk], sb + SM_U_LO + abase + kk * 32);
        }
    }

    // ldmatrix lane bases within a V plane (quarter q)
    const uint32_t g1base = (32 * q + (l & 7) + (l >> 4) * 8) * VSTR + (((l >> 3) & 1) * 8) * 2;
    const uint32_t g2base = (32 * q + (l & 7) + ((l >> 3) & 1) * 8) * VSTR + (l >> 4) * 16;

    float num[8][4] = {};
    float den0 = 0.f, den1 = 0.f;
    float m0 = 0.f, m1 = 0.f;

    const int r0 = 16 * m + (l >> 2), r1 = r0 + 8;
    const int cb = 2 * (l & 3);
    const long adjr0 = (long)(u0 + r0) * I_DIM + 32 * q + cb + (long)tg0 * BN;
    const long adjr1 = adjr0 + 8L * I_DIM;

    int bcur = 0;                    // buffer index t % 3

    #pragma unroll 1
    for (int t = 0; t < NTC; t++) {
        const int bnext = (bcur == 2) ? 0 : bcur + 1;

        // stage tile t+1 into buf bnext (1-ahead)
        if (t + 1 < NTC) {
            const long srcoff = (long)(tg0 + t + 1) * ROWB;
            const uint32_t dh = sb + SM_VHI + bnext * ROWB;
            const uint32_t dl = sb + SM_VLO + bnext * ROWB;
            for (int idx = tid; idx < 1152; idx += 256) {
                cp16(dh + idx * 16, vhib + srcoff + idx * 16);
                cp16(dl + idx * 16, vlob + srcoff + idx * 16);
            }
        }
        CP_COMMIT();

        // adj for this tile (overlaps the wait)
        int2 a0r[4], a1r[4];
        {
            const int2* p0 = (const int2*)(adj + adjr0 + (long)t * BN);
            const int2* p1 = (const int2*)(adj + adjr1 + (long)t * BN);
            #pragma unroll
            for (int nt = 0; nt < 4; nt++) { a0r[nt] = p0[4 * nt]; a1r[nt] = p1[4 * nt]; }
        }

        CP_WAIT1();
        __syncthreads();                 // THE one barrier per tile

        const uint32_t vhi = sb + SM_VHI + bcur * ROWB;
        const uint32_t vlo = sb + SM_VLO + bcur * ROWB;

        // ---- GEMM1(t): S[16 x 32] = U x V^T, round-robin across accumulators ----
        float s[4][4] = {};
        #pragma unroll
        for (int kk = 0; kk < 4; kk++) {
            const uint32_t off0 = kk * 32;
            const uint32_t off1 = 16 * VSTR + kk * 32;
            uint32_t b0h[4], b1h[4], b0l[4], b1l[4];
            ldsm4(b0h, vhi + g1base + off0);
            ldsm4(b1h, vhi + g1base + off1);
            ldsm4(b0l, vlo + g1base + off0);
            ldsm4(b1l, vlo + g1base + off1);
            // term 1 (uh*vh) across all 4 accumulators
            mma16816(s[0], auh[kk], b0h[0], b0h[1]);
            mma16816(s[1], auh[kk], b0h[2], b0h[3]);
            mma16816(s[2], auh[kk], b1h[0], b1h[1]);
            mma16816(s[3], auh[kk], b1h[2], b1h[3]);
            // term 2 (uh*vl)
            mma16816(s[0], auh[kk], b0l[0], b0l[1]);
            mma16816(s[1], auh[kk], b0l[2], b0l[3]);
            mma16816(s[2], auh[kk], b1l[0], b1l[1]);
            mma16816(s[3], auh[kk], b1l[2], b1l[3]);
            // term 3 (ul*vh)
            mma16816(s[0], aul[kk], b0h[0], b0h[1]);
            mma16816(s[1], aul[kk], b0h[2], b0h[3]);
            mma16816(s[2], aul[kk], b1h[0], b1h[1]);
            mma16816(s[3], aul[kk], b1h[2], b1h[3]);
        }

        // ---- epilogue(t): mask, running max, branchless rescale, P'(t) ----
        float mt0 = 0.f, mt1 = 0.f;
        #pragma unroll
        for (int nt = 0; nt < 4; nt++) {
            s[nt][0] = (a0r[nt].x > 0) ? s[nt][0] : 0.f;
            s[nt][1] = (a0r[nt].y > 0) ? s[nt][1] : 0.f;
            s[nt][2] = (a1r[nt].x > 0) ? s[nt][2] : 0.f;
            s[nt][3] = (a1r[nt].y > 0) ? s[nt][3] : 0.f;
            mt0 = fmaxf(mt0, fmaxf(s[nt][0], s[nt][1]));
            mt1 = fmaxf(mt1, fmaxf(s[nt][2], s[nt][3]));
        }
        mt0 = fmaxf(mt0, __shfl_xor_sync(0xffffffffu, mt0, 1));
        mt0 = fmaxf(mt0, __shfl_xor_sync(0xffffffffu, mt0, 2));
        mt1 = fmaxf(mt1, __shfl_xor_sync(0xffffffffu, mt1, 1));
        mt1 = fmaxf(mt1, __shfl_xor_sync(0xffffffffu, mt1, 2));

        const float m0n = fmaxf(m0, mt0), m1n = fmaxf(m1, mt1);
        const float sc0 = __expf(m0 - m0n), sc1 = __expf(m1 - m1n);
        den0 *= sc0; den1 *= sc1;
        #pragma unroll
        for (int nd = 0; nd < 8; nd++) {
            num[nd][0] *= sc0; num[nd][1] *= sc0;
            num[nd][2] *= sc1; num[nd][3] *= sc1;
        }
        m0 = m0n; m1 = m1n;

        uint32_t pA[4], pB[4];
        #pragma unroll
        for (int nt = 0; nt < 4; nt++) {
            float p00 = __expf(s[nt][0] - m0), p01 = __expf(s[nt][1] - m0);
            float p10 = __expf(s[nt][2] - m1), p11 = __expf(s[nt][3] - m1);
            den0 += p00 + p01;
            den1 += p10 + p11;
            pA[nt] = packh2(p00, p01);
            pB[nt] = packh2(p10, p11);
        }

        // ---- GEMM2(t): num += P'(t) x V(t) (hi plane, already round-robin) ----
        #pragma unroll
        for (int kk = 0; kk < 2; kk++) {
            const uint32_t ah0 = pA[2 * kk], ah1 = pB[2 * kk], ah2 = pA[2 * kk + 1], ah3 = pB[2 * kk + 1];
            #pragma unroll
            for (int jd = 0; jd < 4; jd++) {
                const uint32_t off = kk * (16 * VSTR) + jd * 32;
                uint32_t bh0, bh1, bh2, bh3;
                ldsm4t(bh0, bh1, bh2, bh3, vhi + g2base + off);
                mma16816v(num[2 * jd],     ah0, ah1, ah2, ah3, bh0, bh1);
                mma16816v(num[2 * jd + 1], ah0, ah1, ah2, ah3, bh2, bh3);
            }
        }
        // NO end-of-loop sync: 3 buffers make one-iteration warp skew safe.
        bcur = bnext;
    }
    __syncthreads();        // all V reads complete before aliasing smem

    // ---- end phase: merge (m, den, num) across item quarters; write partials ----
    float* dens = (float*)(smc + SM_DEN);          // [4][32]
    float* ms   = (float*)(smc + SM_DEN + 512);    // [4][32]
    float* numq = (float*)(smc + SM_NUMA);         // [4][32][68] fp32 (aliases V)

    if ((l & 3) == 0) { ms[q * 32 + r0] = m0; ms[q * 32 + r1] = m1; }
    __syncthreads();
    const float M0 = fmaxf(fmaxf(ms[r0], ms[32 + r0]), fmaxf(ms[64 + r0], ms[96 + r0]));
    const float M1 = fmaxf(fmaxf(ms[r1], ms[32 + r1]), fmaxf(ms[64 + r1], ms[96 + r1]));
    const float f0 = __expf(m0 - M0), f1 = __expf(m1 - M1);

    #pragma unroll
    for (int nd = 0; nd < 8; nd++) {
        *(float2*)(numq + q * (32 * 68) + r0 * 68 + 8 * nd + cb) =
            make_float2(num[nd][0] * f0, num[nd][1] * f0);
        *(float2*)(numq + q * (32 * 68) + r1 * 68 + 8 * nd + cb) =
            make_float2(num[nd][2] * f1, num[nd][3] * f1);
    }
    den0 += __shfl_xor_sync(0xffffffffu, den0, 1);
    den0 += __shfl_xor_sync(0xffffffffu, den0, 2);
    den1 += __shfl_xor_sync(0xffffffffu, den1, 1);
    den1 += __shfl_xor_sync(0xffffffffu, den1, 2);
    if ((l & 3) == 0) { dens[q * 32 + r0] = den0 * f0; dens[q * 32 + r1] = den1 * f1; }
    __syncthreads();

    // reduce num across q and write partial numerator to gmem
    {
        const int row = tid >> 3, c0 = (tid & 7) * 8;
        float acc[8];
        #pragma unroll
        for (int j = 0; j < 8; j++) acc[j] = numq[row * 68 + c0 + j];
        #pragma unroll
        for (int qq = 1; qq < 4; qq++)
            #pragma unroll
            for (int j = 0; j < 8; j++)
                acc[j] += numq[qq * (32 * 68) + row * 68 + c0 + j];
        *(float4*)&g_pnum[bid][row][c0]     = make_float4(acc[0], acc[1], acc[2], acc[3]);
        *(float4*)&g_pnum[bid][row][c0 + 4] = make_float4(acc[4], acc[5], acc[6], acc[7]);
    }
    if (tid < 32) {
        g_pden[bid][tid] = dens[tid] + dens[32 + tid] + dens[64 + tid] + dens[96 + tid];
        g_pm[bid][tid]   = fmaxf(fmaxf(ms[tid], ms[32 + tid]), fmaxf(ms[64 + tid], ms[96 + tid]));
    }
}

// ---- merge the NCH item-chunk partials per u-block, normalize, apply W ----
__global__ void __launch_bounds__(256)
merge_kernel(const float* __restrict__ Wmat, float* __restrict__ out)
{
    __shared__ float Ws[4096];
    __shared__ float amg[BM * 68];
    __shared__ float dinvs[BM];
    const int tid = threadIdx.x;
    const int ub  = blockIdx.x;
    const int base = ub * 4;

    #pragma unroll
    for (int j = 0; j < 16; j++) Ws[tid + 256 * j] = Wmat[tid + 256 * j];

    const int row = tid >> 3, c0 = (tid & 7) * 8;

    const float mm0 = g_pm[base + 0][row], mm1 = g_pm[base + 1][row];
    const float mm2 = g_pm[base + 2][row], mm3 = g_pm[base + 3][row];
    const float Mg  = fmaxf(fmaxf(mm0, mm1), fmaxf(mm2, mm3));
    const float w0 = __expf(mm0 - Mg), w1 = __expf(mm1 - Mg);
    const float w2 = __expf(mm2 - Mg), w3 = __expf(mm3 - Mg);

    if ((tid & 7) == 0) {
        const float den = w0 * g_pden[base + 0][row] + w1 * g_pden[base + 1][row]
                        + w2 * g_pden[base + 2][row] + w3 * g_pden[base + 3][row];
        dinvs[row] = 1.0f / den;
    }

    float acc[8];
    {
        const float4* n0 = (const float4*)&g_pnum[base + 0][row][c0];
        const float4* n1 = (const float4*)&g_pnum[base + 1][row][c0];
        const float4* n2 = (const float4*)&g_pnum[base + 2][row][c0];
        const float4* n3 = (const float4*)&g_pnum[base + 3][row][c0];
        #pragma unroll
        for (int h = 0; h < 2; h++) {
            float4 a0 = n0[h], a1 = n1[h], a2 = n2[h], a3 = n3[h];
            acc[4*h + 0] = w0 * a0.x + w1 * a1.x + w2 * a2.x + w3 * a3.x;
            acc[4*h + 1] = w0 * a0.y + w1 * a1.y + w2 * a2.y + w3 * a3.y;
            acc[4*h + 2] = w0 * a0.z + w1 * a1.z + w2 * a2.z + w3 * a3.z;
            acc[4*h + 3] = w0 * a0.w + w1 * a1.w + w2 * a2.w + w3 * a3.w;
        }
    }
    #pragma unroll
    for (int j = 0; j < 8; j++) amg[row * 68 + c0 + j] = acc[j];
    __syncthreads();

    const float dinv = dinvs[row];
    float o[8] = {};
    #pragma unroll 8
    for (int k = 0; k < 64; k++) {
        const float a = amg[row * 68 + k];
        const float4 wv0 = *(const float4*)(Ws + k * 64 + c0);
        const float4 wv1 = *(const float4*)(Ws + k * 64 + c0 + 4);
        o[0] = fmaf(a, wv0.x, o[0]); o[1] = fmaf(a, wv0.y, o[1]);
        o[2] = fmaf(a, wv0.z, o[2]); o[3] = fmaf(a, wv0.w, o[3]);
        o[4] = fmaf(a, wv1.x, o[4]); o[5] = fmaf(a, wv1.y, o[5]);
        o[6] = fmaf(a, wv1.z, o[6]); o[7] = fmaf(a, wv1.w, o[7]);
    }
    float4* op = (float4*)(out + (long)(ub * BM + row) * OUT_DIM + c0);
    op[0] = make_float4(o[0] * dinv, o[1] * dinv, o[2] * dinv, o[3] * dinv);
    op[1] = make_float4(o[4] * dinv, o[5] * dinv, o[6] * dinv, o[7] * dinv);
}

extern "C" void kernel_launch(void* const* d_in, const int* in_sizes, int n_in,
                              void* d_out, int out_size)
{
    const float* user_emb = (const float*)d_in[0];
    const float* item_emb = (const float*)d_in[1];
    const float* Wmat     = (const float*)d_in[2];
    const int*   adj      = (const int*)d_in[3];
    float*       out      = (float*)d_out;

    vsplit_kernel<<<I_DIM * D_DIM / 8 / 256, 256>>>(item_emb);
    cudaFuncSetAttribute(atten_hmma_kernel,
                         cudaFuncAttributeMaxDynamicSharedMemorySize, SMEM_TOTAL);
    atten_hmma_kernel<<<(U_DIM / BM) * NCH, 256, SMEM_TOTAL>>>(user_emb, adj);
    merge_kernel<<<U_DIM / BM, 256>>>(Wmat, out);
}

// round 15
// speedup vs baseline: 1.2770x; 1.1128x over previous
#include <cuda_runtime.h>
#include <cuda_fp16.h>
#include <cstdint>

// AttenConv round 14: per-quarter pipelines (round 13 design, cp geometry FIXED).
// out[u,:] = softmax_i(adj?<U_u,V_i>:0) @ V @ W
// GEMM1: fp16 hi/lo 3-term; GEMM2: single fp16 term (p' <= 1), inline.
// Each warp only reads V rows of its own quarter -> V stored per-quarter;
// per-tile sync is a 2-warp named barrier (bar.sync 1+q, 64). Warp pairs
// drift independently; pairs' epilogues overlap other pairs' MMA streams.
// FIX vs r13: warp copies exactly its 2304-byte half-slice (guarded loop),
// no overrun past the quarter or past g_vhi/g_vlo.

#define U_DIM   8192
#define I_DIM   16384
#define D_DIM   64
#define OUT_DIM 64
#define BM      32          // users per CTA
#define BN      128         // items per tile
#define NCH     4           // item chunks (CTAs per u-block)
#define NTC     32          // tiles per CTA
#define VSTR    144         // bytes per 64-half row
#define QPLANE  4608        // one quarter plane: 32 rows * 144B
#define QBUF    9216        // hi+lo planes of one quarter buf
#define QSTRIDE 27648       // 3 bufs per quarter

// smem layout: [quarter q][buf 0..2][hi|lo] then den/ms
#define SM_DEN  110592               // dens[4][32] 512 + ms[4][32] 512
#define SM_UH   9216                 // U hi [32][72] = quarter0 buf1 hi
#define SM_UL   13824                // U lo [32][72] = quarter0 buf1 lo
#define SM_NUMA 0                    // end-phase alias: num [4][32][68] fp32
#define SMEM_TOTAL 111616

__device__ __align__(16) __half g_vhi[I_DIM][72];
__device__ __align__(16) __half g_vlo[I_DIM][72];
__device__ __align__(16) float  g_pnum[1024][BM][D_DIM];
__device__ float g_pden[1024][BM];
__device__ float g_pm[1024][BM];

__device__ __forceinline__ uint32_t smem_u32(const void* p) {
    uint32_t a;
    asm("{ .reg .u64 t; cvta.to.shared.u64 t, %1; cvt.u32.u64 %0, t; }" : "=r"(a) : "l"(p));
    return a;
}
__device__ __forceinline__ void cp16(uint32_t dst, const void* src) {
    asm volatile("cp.async.cg.shared.global [%0], [%1], 16;" :: "r"(dst), "l"(src));
}
#define CP_COMMIT() asm volatile("cp.async.commit_group;" ::: "memory")
#define CP_WAIT1()  asm volatile("cp.async.wait_group 1;" ::: "memory")
#define PAIR_BAR(id) asm volatile("bar.sync %0, 64;" :: "r"(id) : "memory")

// NON-volatile: pure register op, lets ptxas schedule MMAs freely.
__device__ __forceinline__ void mma16816(float* d,
                                         const uint32_t* a,
                                         uint32_t b0, uint32_t b1) {
    asm("mma.sync.aligned.m16n8k16.row.col.f32.f16.f16.f32 "
        "{%0,%1,%2,%3},{%4,%5,%6,%7},{%8,%9},{%0,%1,%2,%3};"
        : "+f"(d[0]), "+f"(d[1]), "+f"(d[2]), "+f"(d[3])
        : "r"(a[0]), "r"(a[1]), "r"(a[2]), "r"(a[3]), "r"(b0), "r"(b1));
}
__device__ __forceinline__ void mma16816v(float* d,
                                          uint32_t a0, uint32_t a1, uint32_t a2, uint32_t a3,
                                          uint32_t b0, uint32_t b1) {
    asm("mma.sync.aligned.m16n8k16.row.col.f32.f16.f16.f32 "
        "{%0,%1,%2,%3},{%4,%5,%6,%7},{%8,%9},{%0,%1,%2,%3};"
        : "+f"(d[0]), "+f"(d[1]), "+f"(d[2]), "+f"(d[3])
        : "r"(a0), "r"(a1), "r"(a2), "r"(a3), "r"(b0), "r"(b1));
}
__device__ __forceinline__ void ldsm4(uint32_t* r, uint32_t addr) {
    asm volatile("ldmatrix.sync.aligned.m8n8.x4.shared.b16 {%0,%1,%2,%3}, [%4];"
                 : "=r"(r[0]), "=r"(r[1]), "=r"(r[2]), "=r"(r[3]) : "r"(addr));
}
__device__ __forceinline__ void ldsm4t(uint32_t& r0, uint32_t& r1, uint32_t& r2, uint32_t& r3,
                                       uint32_t addr) {
    asm volatile("ldmatrix.sync.aligned.m8n8.x4.trans.shared.b16 {%0,%1,%2,%3}, [%4];"
                 : "=r"(r0), "=r"(r1), "=r"(r2), "=r"(r3) : "r"(addr));
}
__device__ __forceinline__ uint32_t packh2(float x0, float x1) {
    uint32_t r;
    asm("cvt.rn.f16x2.f32 %0, %1, %2;" : "=r"(r) : "f"(x1), "f"(x0));
    return r;
}
__device__ __forceinline__ void split2h(float x0, float x1, uint32_t& h, uint32_t& l) {
    h = packh2(x0, x1);
    __half2 hv = *(__half2*)&h;
    float2 back = __half22float2(hv);
    l = packh2(x0 - back.x, x1 - back.y);
}

// ---- precompute: split item_emb into fp16 hi/lo planes with VSTR padding ----
__global__ void __launch_bounds__(256)
vsplit_kernel(const float* __restrict__ item_emb)
{
    const int gid  = blockIdx.x * 256 + threadIdx.x;
    const int item = gid >> 3;
    const int d0   = (gid & 7) * 8;
    const float4* vp = (const float4*)(item_emb + (long)item * D_DIM + d0);
    const float4 v0 = vp[0], v1 = vp[1];
    uint32_t h0, l0, h1, l1, h2, l2, h3, l3;
    split2h(v0.x, v0.y, h0, l0); split2h(v0.z, v0.w, h1, l1);
    split2h(v1.x, v1.y, h2, l2); split2h(v1.z, v1.w, h3, l3);
    *(uint4*)&g_vhi[item][d0] = make_uint4(h0, h1, h2, h3);
    *(uint4*)&g_vlo[item][d0] = make_uint4(l0, l1, l2, l3);
}

__global__ void __launch_bounds__(256, 2)
atten_hmma_kernel(const float* __restrict__ user_emb,
                  const int*   __restrict__ adj)
{
    extern __shared__ __align__(128) char smc[];
    const uint32_t sb = smem_u32(smc);
    const int tid = threadIdx.x;
    const int bid = blockIdx.x;
    const int ub  = bid >> 2;       // u-block
    const int ch  = bid & 3;        // item chunk
    const int w   = tid >> 5;
    const int l   = tid & 31;
    const int m   = w & 1;          // user group: rows 16m..16m+15
    const int q   = w >> 1;         // item quarter within tile
    const int u0  = ub * BM;
    const int tg0 = ch * NTC;       // first global tile index

    const char* vhib = (const char*)g_vhi;
    const char* vlob = (const char*)g_vlo;

    // per-warp cp geometry: warp copies its 2304-byte HALF of the quarter
    // slice (half = m*2304), 144 cp16 ops per plane via guarded loop.
    const uint32_t qbase = (uint32_t)q * QSTRIDE;        // smem quarter base
    const uint32_t half  = (uint32_t)m * 2304;

    // ---- prologue: stage U hi/lo (quarter0 buf1); cp tile 0 into buf 0 ----
    {
        const int row = tid >> 3, d0 = (tid & 7) * 8;
        const float4* up = (const float4*)(user_emb + (long)(u0 + row) * D_DIM + d0);
        const float4 v0 = up[0], v1 = up[1];
        uint32_t h0, l0h, h1, l1h, h2, l2h, h3, l3h;
        split2h(v0.x, v0.y, h0, l0h); split2h(v0.z, v0.w, h1, l1h);
        split2h(v1.x, v1.y, h2, l2h); split2h(v1.z, v1.w, h3, l3h);
        *(uint4*)(smc + SM_UH + row * VSTR + d0 * 2) = make_uint4(h0, h1, h2, h3);
        *(uint4*)(smc + SM_UL + row * VSTR + d0 * 2) = make_uint4(l0h, l1h, l2h, l3h);
    }
    {
        const long src = ((long)tg0 * 128 + 32 * q) * VSTR + half;
        const uint32_t dh = sb + qbase + half;       // buf 0 hi, own half
        const uint32_t dl = dh + QPLANE;             // buf 0 lo, own half
        #pragma unroll
        for (int k = 0; k < 5; k++) {
            const int idx = l + 32 * k;
            if (idx < 144) {
                cp16(dh + idx * 16, vhib + src + idx * 16);
                cp16(dl + idx * 16, vlob + src + idx * 16);
            }
        }
    }
    CP_COMMIT();
    __syncthreads();                 // publish U stores

    // ---- persistent U A-fragments (hi/lo fp16) ----
    uint32_t auh[4][4], aul[4][4];
    {
        const uint32_t abase = (16 * m + (l & 15)) * VSTR + (l >> 4) * 16;
        #pragma unroll
        for (int kk = 0; kk < 4; kk++) {
            ldsm4(auh[kk], sb + SM_UH + abase + kk * 32);
            ldsm4(aul[kk], sb + SM_UL + abase + kk * 32);
        }
    }
    __syncthreads();                 // all U reads done before any loop cp
                                     // can clobber quarter0 buf1

    // ldmatrix lane bases WITHIN a quarter plane
    const uint32_t g1base = ((l & 7) + (l >> 4) * 8) * VSTR + ((l >> 3) & 1) * 16;
    const uint32_t g2base = ((l & 7) + ((l >> 3) & 1) * 8) * VSTR + (l >> 4) * 16;

    float num[8][4] = {};
    float den0 = 0.f, den1 = 0.f;
    float m0 = 0.f, m1 = 0.f;

    const int r0 = 16 * m + (l >> 2), r1 = r0 + 8;
    const int cb = 2 * (l & 3);
    const long adjr0 = (long)(u0 + r0) * I_DIM + 32 * q + cb + (long)tg0 * BN;
    const long adjr1 = adjr0 + 8L * I_DIM;
    const int barid = 1 + q;

    int bcur = 0;                    // buffer index t % 3

    #pragma unroll 1
    for (int t = 0; t < NTC; t++) {
        const int bnext = (bcur == 2) ? 0 : bcur + 1;

        // stage this quarter's slice of tile t+1 into buf bnext (own half)
        if (t + 1 < NTC) {
            const long src = (((long)(tg0 + t + 1)) * 128 + 32 * q) * VSTR + half;
            const uint32_t dh = sb + qbase + bnext * QBUF + half;
            const uint32_t dl = dh + QPLANE;
            #pragma unroll
            for (int k = 0; k < 5; k++) {
                const int idx = l + 32 * k;
                if (idx < 144) {
                    cp16(dh + idx * 16, vhib + src + idx * 16);
                    cp16(dl + idx * 16, vlob + src + idx * 16);
                }
            }
        }
        CP_COMMIT();

        // adj for this tile (overlaps the wait)
        int2 a0r[4], a1r[4];
        {
            const int2* p0 = (const int2*)(adj + adjr0 + (long)t * BN);
            const int2* p1 = (const int2*)(adj + adjr1 + (long)t * BN);
            #pragma unroll
            for (int nt = 0; nt < 4; nt++) { a0r[nt] = p0[4 * nt]; a1r[nt] = p1[4 * nt]; }
        }

        CP_WAIT1();                  // own tile-t slice complete
        PAIR_BAR(barid);             // partner's slice complete + published

        const uint32_t vhi = sb + qbase + bcur * QBUF;
        const uint32_t vlo = vhi + QPLANE;

        // ---- GEMM1(t): S[16 x 32] = U x V^T, round-robin across accumulators ----
        float s[4][4] = {};
        #pragma unroll
        for (int kk = 0; kk < 4; kk++) {
            const uint32_t off0 = kk * 32;
            const uint32_t off1 = 16 * VSTR + kk * 32;
            uint32_t b0h[4], b1h[4], b0l[4], b1l[4];
            ldsm4(b0h, vhi + g1base + off0);
            ldsm4(b1h, vhi + g1base + off1);
            ldsm4(b0l, vlo + g1base + off0);
            ldsm4(b1l, vlo + g1base + off1);
            mma16816(s[0], auh[kk], b0h[0], b0h[1]);
            mma16816(s[1], auh[kk], b0h[2], b0h[3]);
            mma16816(s[2], auh[kk], b1h[0], b1h[1]);
            mma16816(s[3], auh[kk], b1h[2], b1h[3]);
            mma16816(s[0], auh[kk], b0l[0], b0l[1]);
            mma16816(s[1], auh[kk], b0l[2], b0l[3]);
            mma16816(s[2], auh[kk], b1l[0], b1l[1]);
            mma16816(s[3], auh[kk], b1l[2], b1l[3]);
            mma16816(s[0], aul[kk], b0h[0], b0h[1]);
            mma16816(s[1], aul[kk], b0h[2], b0h[3]);
            mma16816(s[2], aul[kk], b1h[0], b1h[1]);
            mma16816(s[3], aul[kk], b1h[2], b1h[3]);
        }

        // ---- epilogue(t): mask, running max, branchless rescale, P'(t) ----
        float mt0 = 0.f, mt1 = 0.f;
        #pragma unroll
        for (int nt = 0; nt < 4; nt++) {
            s[nt][0] = (a0r[nt].x > 0) ? s[nt][0] : 0.f;
            s[nt][1] = (a0r[nt].y > 0) ? s[nt][1] : 0.f;
            s[nt][2] = (a1r[nt].x > 0) ? s[nt][2] : 0.f;
            s[nt][3] = (a1r[nt].y > 0) ? s[nt][3] : 0.f;
            mt0 = fmaxf(mt0, fmaxf(s[nt][0], s[nt][1]));
            mt1 = fmaxf(mt1, fmaxf(s[nt][2], s[nt][3]));
        }
        mt0 = fmaxf(mt0, __shfl_xor_sync(0xffffffffu, mt0, 1));
        mt0 = fmaxf(mt0, __shfl_xor_sync(0xffffffffu, mt0, 2));
        mt1 = fmaxf(mt1, __shfl_xor_sync(0xffffffffu, mt1, 1));
        mt1 = fmaxf(mt1, __shfl_xor_sync(0xffffffffu, mt1, 2));

        const float m0n = fmaxf(m0, mt0), m1n = fmaxf(m1, mt1);
        const float sc0 = __expf(m0 - m0n), sc1 = __expf(m1 - m1n);
        den0 *= sc0; den1 *= sc1;
        #pragma unroll
        for (int nd = 0; nd < 8; nd++) {
            num[nd][0] *= sc0; num[nd][1] *= sc0;
            num[nd][2] *= sc1; num[nd][3] *= sc1;
        }
        m0 = m0n; m1 = m1n;

        uint32_t pA[4], pB[4];
        #pragma unroll
        for (int nt = 0; nt < 4; nt++) {
            float p00 = __expf(s[nt][0] - m0), p01 = __expf(s[nt][1] - m0);
            float p10 = __expf(s[nt][2] - m1), p11 = __expf(s[nt][3] - m1);
            den0 += p00 + p01;
            den1 += p10 + p11;
            pA[nt] = packh2(p00, p01);
            pB[nt] = packh2(p10, p11);
        }

        // ---- GEMM2(t): num += P'(t) x V(t) (hi plane) ----
        #pragma unroll
        for (int kk = 0; kk < 2; kk++) {
            const uint32_t ah0 = pA[2 * kk], ah1 = pB[2 * kk], ah2 = pA[2 * kk + 1], ah3 = pB[2 * kk + 1];
            #pragma unroll
            for (int jd = 0; jd < 4; jd++) {
                const uint32_t off = kk * (16 * VSTR) + jd * 32;
                uint32_t bh0, bh1, bh2, bh3;
                ldsm4t(bh0, bh1, bh2, bh3, vhi + g2base + off);
                mma16816v(num[2 * jd],     ah0, ah1, ah2, ah3, bh0, bh1);
                mma16816v(num[2 * jd + 1], ah0, ah1, ah2, ah3, bh2, bh3);
            }
        }
        bcur = bnext;
    }
    __syncthreads();        // all V reads complete before aliasing smem

    // ---- end phase: merge (m, den, num) across item quarters; write partials ----
    float* dens = (float*)(smc + SM_DEN);          // [4][32]
    float* ms   = (float*)(smc + SM_DEN + 512);    // [4][32]
    float* numq = (float*)(smc + SM_NUMA);         // [4][32][68] fp32 (aliases V)

    if ((l & 3) == 0) { ms[q * 32 + r0] = m0; ms[q * 32 + r1] = m1; }
    __syncthreads();
    const float M0 = fmaxf(fmaxf(ms[r0], ms[32 + r0]), fmaxf(ms[64 + r0], ms[96 + r0]));
    const float M1 = fmaxf(fmaxf(ms[r1], ms[32 + r1]), fmaxf(ms[64 + r1], ms[96 + r1]));
    const float f0 = __expf(m0 - M0), f1 = __expf(m1 - M1);

    #pragma unroll
    for (int nd = 0; nd < 8; nd++) {
        *(float2*)(numq + q * (32 * 68) + r0 * 68 + 8 * nd + cb) =
            make_float2(num[nd][0] * f0, num[nd][1] * f0);
        *(float2*)(numq + q * (32 * 68) + r1 * 68 + 8 * nd + cb) =
            make_float2(num[nd][2] * f1, num[nd][3] * f1);
    }
    den0 += __shfl_xor_sync(0xffffffffu, den0, 1);
    den0 += __shfl_xor_sync(0xffffffffu, den0, 2);
    den1 += __shfl_xor_sync(0xffffffffu, den1, 1);
    den1 += __shfl_xor_sync(0xffffffffu, den1, 2);
    if ((l & 3) == 0) { dens[q * 32 + r0] = den0 * f0; dens[q * 32 + r1] = den1 * f1; }
    __syncthreads();

    // reduce num across q and write partial numerator to gmem
    {
        const int row = tid >> 3, c0 = (tid & 7) * 8;
        float acc[8];
        #pragma unroll
        for (int j = 0; j < 8; j++) acc[j] = numq[row * 68 + c0 + j];
        #pragma unroll
        for (int qq = 1; qq < 4; qq++)
            #pragma unroll
            for (int j = 0; j < 8; j++)
                acc[j] += numq[qq * (32 * 68) + row * 68 + c0 + j];
        *(float4*)&g_pnum[bid][row][c0]     = make_float4(acc[0], acc[1], acc[2], acc[3]);
        *(float4*)&g_pnum[bid][row][c0 + 4] = make_float4(acc[4], acc[5], acc[6], acc[7]);
    }
    if (tid < 32) {
        g_pden[bid][tid] = dens[tid] + dens[32 + tid] + dens[64 + tid] + dens[96 + tid];
        g_pm[bid][tid]   = fmaxf(fmaxf(ms[tid], ms[32 + tid]), fmaxf(ms[64 + tid], ms[96 + tid]));
    }
}

// ---- merge the NCH item-chunk partials per u-block, normalize, apply W ----
__global__ void __launch_bounds__(256)
merge_kernel(const float* __restrict__ Wmat, float* __restrict__ out)
{
    __shared__ float Ws[4096];
    __shared__ float amg[BM * 68];
    __shared__ float dinvs[BM];
    const int tid = threadIdx.x;
    const int ub  = blockIdx.x;
    const int base = ub * 4;

    #pragma unroll
    for (int j = 0; j < 16; j++) Ws[tid + 256 * j] = Wmat[tid + 256 * j];

    const int row = tid >> 3, c0 = (tid & 7) * 8;

    const float mm0 = g_pm[base + 0][row], mm1 = g_pm[base + 1][row];
    const float mm2 = g_pm[base + 2][row], mm3 = g_pm[base + 3][row];
    const float Mg  = fmaxf(fmaxf(mm0, mm1), fmaxf(mm2, mm3));
    const float w0 = __expf(mm0 - Mg), w1 = __expf(mm1 - Mg);
    const float w2 = __expf(mm2 - Mg), w3 = __expf(mm3 - Mg);

    if ((tid & 7) == 0) {
        const float den = w0 * g_pden[base + 0][row] + w1 * g_pden[base + 1][row]
                        + w2 * g_pden[base + 2][row] + w3 * g_pden[base + 3][row];
        dinvs[row] = 1.0f / den;
    }

    float acc[8];
    {
        const float4* n0 = (const float4*)&g_pnum[base + 0][row][c0];
        const float4* n1 = (const float4*)&g_pnum[base + 1][row][c0];
        const float4* n2 = (const float4*)&g_pnum[base + 2][row][c0];
        const float4* n3 = (const float4*)&g_pnum[base + 3][row][c0];
        #pragma unroll
        for (int h = 0; h < 2; h++) {
            float4 a0 = n0[h], a1 = n1[h], a2 = n2[h], a3 = n3[h];
            acc[4*h + 0] = w0 * a0.x + w1 * a1.x + w2 * a2.x + w3 * a3.x;
            acc[4*h + 1] = w0 * a0.y + w1 * a1.y + w2 * a2.y + w3 * a3.y;
            acc[4*h + 2] = w0 * a0.z + w1 * a1.z + w2 * a2.z + w3 * a3.z;
            acc[4*h + 3] = w0 * a0.w + w1 * a1.w + w2 * a2.w + w3 * a3.w;
        }
    }
    #pragma unroll
    for (int j = 0; j < 8; j++) amg[row * 68 + c0 + j] = acc[j];
    __syncthreads();

    const float dinv = dinvs[row];
    float o[8] = {};
    #pragma unroll 8
    for (int k = 0; k < 64; k++) {
        const float a = amg[row * 68 + k];
        const float4 wv0 = *(const float4*)(Ws + k * 64 + c0);
        const float4 wv1 = *(const float4*)(Ws + k * 64 + c0 + 4);
        o[0] = fmaf(a, wv0.x, o[0]); o[1] = fmaf(a, wv0.y, o[1]);
        o[2] = fmaf(a, wv0.z, o[2]); o[3] = fmaf(a, wv0.w, o[3]);
        o[4] = fmaf(a, wv1.x, o[4]); o[5] = fmaf(a, wv1.y, o[5]);
        o[6] = fmaf(a, wv1.z, o[6]); o[7] = fmaf(a, wv1.w, o[7]);
    }
    float4* op = (float4*)(out + (long)(ub * BM + row) * OUT_DIM + c0);
    op[0] = make_float4(o[0] * dinv, o[1] * dinv, o[2] * dinv, o[3] * dinv);
    op[1] = make_float4(o[4] * dinv, o[5] * dinv, o[6] * dinv, o[7] * dinv);
}

extern "C" void kernel_launch(void* const* d_in, const int* in_sizes, int n_in,
                              void* d_out, int out_size)
{
    const float* user_emb = (const float*)d_in[0];
    const float* item_emb = (const float*)d_in[1];
    const float* Wmat     = (const float*)d_in[2];
    const int*   adj      = (const int*)d_in[3];
    float*       out      = (float*)d_out;

    vsplit_kernel<<<I_DIM * D_DIM / 8 / 256, 256>>>(item_emb);
    cudaFuncSetAttribute(atten_hmma_kernel,
                         cudaFuncAttributeMaxDynamicSharedMemorySize, SMEM_TOTAL);
    atten_hmma_kernel<<<(U_DIM / BM) * NCH, 256, SMEM_TOTAL>>>(user_emb, adj);
    merge_kernel<<<U_DIM / BM, 256>>>(Wmat, out);
}